// round 3
// baseline (speedup 1.0000x reference)
#include <cuda_runtime.h>
#include <cuda_bf16.h>
#include <math.h>

// Problem constants
#define BATCH 2
#define SEQL  2048
#define DIM   768
#define NHEAD 12
#define DHEAD 64
#define DFF   3072
#define DFFH  1536
#define NROWS (BATCH*SEQL)          // 4096

// ---------------- scratch (static device globals; no allocation) ----------------
__device__ float g_mask[DIM];
__device__ float g_xn [NROWS*DIM];
__device__ float g_q  [NROWS*DIM];
__device__ float g_k  [NROWS*DIM];
__device__ float g_v  [NROWS*DIM];
__device__ float g_attn[NROWS*DIM];
__device__ float g_x1 [NROWS*DIM];
__device__ float g_xm [NROWS*DIM];
__device__ float g_xs [NROWS*DIM];
__device__ float g_h1 [NROWS*DFF];
__device__ float g_ht [NROWS*DFFH];
__device__ float g_hs [NROWS*DFFH];

// ---------------- helpers ----------------
__device__ __forceinline__ float gelu_f(float x) {
    return 0.5f * x * (1.f + erff(x * 0.70710678118654752f));
}
__device__ __forceinline__ float silu_f(float x) {
    return x / (1.f + expf(-x));
}

// ---------------- timelike_mask decode (dtype-robust: f32 / i32 / bool8) ----------------
__global__ void decode_mask_kernel(const void* __restrict__ raw) {
    __shared__ int cls;  // 0=float32, 1=int32, 2=byte
    if (threadIdx.x == 0) {
        const unsigned* w = (const unsigned*)raw;
        int isFloat = 0, isByte = 0;
        for (int i = 0; i < 192; i++) {       // 192 words is safe for every interpretation
            unsigned v = w[i];
            if (v == 0x3F800000u) isFloat = 1;
            if (v != 0u) {
                bool bytes01 = true, hi = false;
                for (int b = 0; b < 4; b++) {
                    unsigned by = (v >> (8*b)) & 0xffu;
                    if (by > 1u) bytes01 = false;
                    if (b > 0 && by) hi = true;
                }
                if (bytes01 && hi) isByte = 1;
            }
        }
        cls = isFloat ? 0 : (isByte ? 2 : 1);
    }
    __syncthreads();
    int c = cls;
    for (int i = threadIdx.x; i < DIM; i += blockDim.x) {
        float mv;
        if (c == 0)      mv = ((const float*)raw)[i];
        else if (c == 1) mv = (float)(((const int*)raw)[i] != 0);
        else             mv = (float)(((const unsigned char*)raw)[i] != 0);
        g_mask[i] = mv;
    }
}

// ---------------- Minkowski LayerNorm: one block (256 thr) per row ----------------
__global__ __launch_bounds__(256) void mink_norm_kernel(
    const float* __restrict__ x, const float* __restrict__ w,
    const float* __restrict__ bb, float* __restrict__ out)
{
    __shared__ float sA[8], sB[8];
    int row = blockIdx.x, t = threadIdx.x;
    const float* xr = x + (size_t)row * DIM;
    float v0 = xr[t], v1 = xr[t+256], v2 = xr[t+512];
    int lane = t & 31, wp = t >> 5;

    float s = v0 + v1 + v2;
    #pragma unroll
    for (int o = 16; o; o >>= 1) s += __shfl_xor_sync(0xffffffffu, s, o);
    if (!lane) sA[wp] = s;
    __syncthreads();
    float tot = 0.f;
    #pragma unroll
    for (int i = 0; i < 8; i++) tot += sA[i];
    float mean = tot * (1.f / DIM);

    float c0 = v0 - mean, c1 = v1 - mean, c2 = v2 - mean;
    float m0 = g_mask[t], m1 = g_mask[t+256], m2 = g_mask[t+512];
    float s2  = c0*c0 + c1*c1 + c2*c2;
    float s2m = c0*c0*m0 + c1*c1*m1 + c2*c2*m2;
    #pragma unroll
    for (int o = 16; o; o >>= 1) {
        s2  += __shfl_xor_sync(0xffffffffu, s2,  o);
        s2m += __shfl_xor_sync(0xffffffffu, s2m, o);
    }
    __syncthreads();
    if (!lane) { sA[wp] = s2; sB[wp] = s2m; }
    __syncthreads();
    float S2 = 0.f, S2m = 0.f;
    #pragma unroll
    for (int i = 0; i < 8; i++) { S2 += sA[i]; S2m += sB[i]; }

    float var = S2 * (1.f / DIM);
    float eta = S2 - 2.f * S2m;     // sum(sq*(1-m)) - sum(sq*m)
    float kk  = 0.5f * (rsqrtf(var + 1e-5f) + rsqrtf(fabsf(eta) + 1e-5f));

    size_t o0 = (size_t)row * DIM + t;
    out[o0]       = w[t]     * (c0 * kk) + bb[t];
    out[o0 + 256] = w[t+256] * (c1 * kk) + bb[t+256];
    out[o0 + 512] = w[t+512] * (c2 * kk) + bb[t+512];
}

// ---------------- generic NT SGEMM: C = ep(alpha, A(MxK) @ B(NxK)^T) ----------------
// ACT: 0 none, 1 gelu(exact), 2 silu.  act applied BEFORE alpha.
// resid != null  -> += resid ;  accumulate -> += existing C
template<int ACT>
__global__ __launch_bounds__(256) void sgemm_nt(
    const float* __restrict__ A, const float* __restrict__ B,
    float* __restrict__ C, const float* __restrict__ resid,
    int M, int N, int K, float alpha, int accumulate)
{
    __shared__ float As[16][68];
    __shared__ float Bs[16][68];
    int tid = threadIdx.x;
    int tx = tid & 15, ty = tid >> 4;
    int bm = blockIdx.y * 64, bn = blockIdx.x * 64;
    int lrow = tid >> 2;            // 0..63
    int lk   = (tid & 3) << 2;      // 0,4,8,12

    const float* Ap = A + (size_t)(bm + lrow) * K + lk;
    const float* Bp = B + (size_t)(bn + lrow) * K + lk;

    float acc[4][4] = {};
    int nk = K >> 4;
    for (int kt = 0; kt < nk; kt++) {
        float4 av = *(const float4*)Ap;
        float4 bv = *(const float4*)Bp;
        As[lk+0][lrow] = av.x; As[lk+1][lrow] = av.y;
        As[lk+2][lrow] = av.z; As[lk+3][lrow] = av.w;
        Bs[lk+0][lrow] = bv.x; Bs[lk+1][lrow] = bv.y;
        Bs[lk+2][lrow] = bv.z; Bs[lk+3][lrow] = bv.w;
        __syncthreads();
        #pragma unroll
        for (int k = 0; k < 16; k++) {
            float4 a = *(const float4*)&As[k][ty << 2];
            float4 b = *(const float4*)&Bs[k][tx << 2];
            float ar[4] = {a.x, a.y, a.z, a.w};
            float br[4] = {b.x, b.y, b.z, b.w};
            #pragma unroll
            for (int i = 0; i < 4; i++)
                #pragma unroll
                for (int j = 0; j < 4; j++)
                    acc[i][j] += ar[i] * br[j];
        }
        __syncthreads();
        Ap += 16; Bp += 16;
    }

    #pragma unroll
    for (int i = 0; i < 4; i++) {
        size_t r = (size_t)(bm + (ty << 2) + i) * N + bn + (tx << 2);
        float vv[4];
        #pragma unroll
        for (int j = 0; j < 4; j++) {
            float t = acc[i][j];
            if (ACT == 1) t = gelu_f(t);
            else if (ACT == 2) t = silu_f(t);
            vv[j] = t * alpha;
        }
        if (resid) {
            float4 rv = *(const float4*)(resid + r);
            vv[0] += rv.x; vv[1] += rv.y; vv[2] += rv.z; vv[3] += rv.w;
        }
        if (accumulate) {
            float4 cv = *(const float4*)(C + r);
            vv[0] += cv.x; vv[1] += cv.y; vv[2] += cv.z; vv[3] += cv.w;
        }
        *(float4*)(C + r) = make_float4(vv[0], vv[1], vv[2], vv[3]);
    }
}

// ---------------- fold Lorentz sf into Q:  Qeff = Q * (1 - 0.5*sf*m) ----------------
__global__ __launch_bounds__(256) void qeff_kernel(float* __restrict__ q)
{
    int gw   = (blockIdx.x * blockDim.x + threadIdx.x) >> 5;
    int lane = threadIdx.x & 31;
    if (gw >= NROWS * NHEAD) return;
    int row = gw / NHEAD, h = gw % NHEAD;
    float* qp = q + (size_t)row * DIM + h * DHEAD;
    float a = qp[lane], c = qp[lane + 32];
    float ma = g_mask[h * DHEAD + lane], mc = g_mask[h * DHEAD + lane + 32];
    float qn2  = a*a + c*c;
    float qtn2 = a*a*ma + c*c*mc;
    #pragma unroll
    for (int o = 16; o; o >>= 1) {
        qn2  += __shfl_xor_sync(0xffffffffu, qn2,  o);
        qtn2 += __shfl_xor_sync(0xffffffffu, qtn2, o);
    }
    float qtn = sqrtf(qtn2);
    float sf  = (qtn > 1e-6f) ? sqrtf(qn2) / fmaxf(qtn, 1e-8f) : 0.f;
    qp[lane]      = a * (1.f - 0.5f * sf * ma);
    qp[lane + 32] = c * (1.f - 0.5f * sf * mc);
}

// ---------------- causal flash attention, fp32, 64x64 tiles ----------------
#define FA_STRIDE 68
#define FA_SMEM   (3 * 64 * FA_STRIDE * 4)

__device__ __forceinline__ void load_tile_T(float* dst, const float* src, int tid) {
    #pragma unroll
    for (int it = 0; it < 4; it++) {
        int idx = tid + it * 256;
        int r = idx >> 4;
        int d4 = (idx & 15) << 2;
        float4 v = *(const float4*)(src + (size_t)r * DIM + d4);
        dst[(d4+0)*FA_STRIDE + r] = v.x; dst[(d4+1)*FA_STRIDE + r] = v.y;
        dst[(d4+2)*FA_STRIDE + r] = v.z; dst[(d4+3)*FA_STRIDE + r] = v.w;
    }
}
__device__ __forceinline__ void load_tile_R(float* dst, const float* src, int tid) {
    #pragma unroll
    for (int it = 0; it < 4; it++) {
        int idx = tid + it * 256;
        int r = idx >> 4;
        int d4 = (idx & 15) << 2;
        *(float4*)(dst + r * FA_STRIDE + d4) = *(const float4*)(src + (size_t)r * DIM + d4);
    }
}

__global__ __launch_bounds__(256) void flash_attn_kernel(
    const float* __restrict__ Q, const float* __restrict__ K,
    const float* __restrict__ V, float* __restrict__ O)
{
    extern __shared__ float sm[];
    float* Qt   = sm;                        // [64 d][68]: Qt[d][i]
    float* KtPt = sm + 64 * FA_STRIDE;       // Kt[d][j]  then Pt[j][i]
    float* Vs   = sm + 2 * 64 * FA_STRIDE;   // Vs[j][d]

    int tid = threadIdx.x;
    int tx = tid & 15, ty = tid >> 4;
    int bid = blockIdx.x;
    int qt = 31 - bid / 24;                  // long blocks first
    int bh = bid % 24;
    int b = bh / NHEAD, h = bh % NHEAD;
    const size_t head_off = (size_t)b * SEQL * DIM + (size_t)h * DHEAD;

    load_tile_T(Qt, Q + head_off + (size_t)qt * 64 * DIM, tid);

    float acc[4][4] = {};
    float mrun[4] = {-1e30f, -1e30f, -1e30f, -1e30f};
    float lrun[4] = {};

    for (int kt = 0; kt <= qt; kt++) {
        load_tile_T(KtPt, K + head_off + (size_t)kt * 64 * DIM, tid);
        load_tile_R(Vs,   V + head_off + (size_t)kt * 64 * DIM, tid);
        __syncthreads();

        float s[4][4] = {};
        #pragma unroll 16
        for (int d = 0; d < 64; d++) {
            float4 a = *(const float4*)&Qt[d * FA_STRIDE + (ty << 2)];
            float4 bb = *(const float4*)&KtPt[d * FA_STRIDE + (tx << 2)];
            float ar[4] = {a.x, a.y, a.z, a.w};
            float br[4] = {bb.x, bb.y, bb.z, bb.w};
            #pragma unroll
            for (int i = 0; i < 4; i++)
                #pragma unroll
                for (int j = 0; j < 4; j++)
                    s[i][j] += ar[i] * br[j];
        }
        #pragma unroll
        for (int i = 0; i < 4; i++)
            #pragma unroll
            for (int j = 0; j < 4; j++)
                s[i][j] *= 0.125f;                     // 1/sqrt(64)

        if (kt == qt) {
            #pragma unroll
            for (int i = 0; i < 4; i++)
                #pragma unroll
                for (int j = 0; j < 4; j++)
                    if ((tx << 2) + j > (ty << 2) + i) s[i][j] = -1e30f;
        }

        #pragma unroll
        for (int i = 0; i < 4; i++) {
            float rm = fmaxf(fmaxf(s[i][0], s[i][1]), fmaxf(s[i][2], s[i][3]));
            #pragma unroll
            for (int o = 8; o; o >>= 1)
                rm = fmaxf(rm, __shfl_xor_sync(0xffffffffu, rm, o));
            float mn = fmaxf(mrun[i], rm);
            float sc = __expf(mrun[i] - mn);
            float rs = 0.f;
            #pragma unroll
            for (int j = 0; j < 4; j++) { s[i][j] = __expf(s[i][j] - mn); rs += s[i][j]; }
            #pragma unroll
            for (int o = 8; o; o >>= 1)
                rs += __shfl_xor_sync(0xffffffffu, rs, o);
            lrun[i] = lrun[i] * sc + rs;
            mrun[i] = mn;
            #pragma unroll
            for (int j = 0; j < 4; j++) acc[i][j] *= sc;
        }

        __syncthreads();   // everyone done reading Kt
        #pragma unroll
        for (int i = 0; i < 4; i++)
            #pragma unroll
            for (int j = 0; j < 4; j++)
                KtPt[((tx << 2) + j) * FA_STRIDE + (ty << 2) + i] = s[i][j];
        __syncthreads();   // P visible

        #pragma unroll 16
        for (int j = 0; j < 64; j++) {
            float4 p  = *(const float4*)&KtPt[j * FA_STRIDE + (ty << 2)];
            float4 vv = *(const float4*)&Vs[j * FA_STRIDE + (tx << 2)];
            float pr[4] = {p.x, p.y, p.z, p.w};
            float vr[4] = {vv.x, vv.y, vv.z, vv.w};
            #pragma unroll
            for (int i = 0; i < 4; i++)
                #pragma unroll
                for (int d = 0; d < 4; d++)
                    acc[i][d] += pr[i] * vr[d];
        }
        __syncthreads();   // done reading before next tile overwrite
    }

    #pragma unroll
    for (int i = 0; i < 4; i++) {
        float inv = 1.f / lrun[i];
        size_t row = (size_t)b * SEQL + qt * 64 + (ty << 2) + i;
        *(float4*)(O + row * DIM + h * DHEAD + (tx << 2)) =
            make_float4(acc[i][0]*inv, acc[i][1]*inv, acc[i][2]*inv, acc[i][3]*inv);
    }
}

// ---------------- elementwise masked splits for FFN ----------------
__global__ __launch_bounds__(256) void apply_mask_kernel(
    const float* __restrict__ xn, float* __restrict__ xm, float* __restrict__ xs)
{
    int i = blockIdx.x * blockDim.x + threadIdx.x;       // float4 index
    float4 v = ((const float4*)xn)[i];
    int col = (i % (DIM / 4)) * 4;
    float m0 = g_mask[col], m1 = g_mask[col+1], m2 = g_mask[col+2], m3 = g_mask[col+3];
    ((float4*)xm)[i] = make_float4(v.x*m0, v.y*m1, v.z*m2, v.w*m3);
    ((float4*)xs)[i] = make_float4(v.x*(1.f-m0), v.y*(1.f-m1), v.z*(1.f-m2), v.w*(1.f-m3));
}

// ---------------- host launcher ----------------
extern "C" void kernel_launch(void* const* d_in, const int* in_sizes, int n_in,
                              void* d_out, int out_size)
{
    const float* x    = (const float*)d_in[0];
    const void*  tmsk = d_in[2];
    const float* Wq   = (const float*)d_in[3];
    const float* Wk   = (const float*)d_in[4];
    const float* Wv   = (const float*)d_in[5];
    const float* Wo   = (const float*)d_in[6];
    const float* w1   = (const float*)d_in[7];
    const float* w2   = (const float*)d_in[8];
    const float* w1t  = (const float*)d_in[9];
    const float* w2t  = (const float*)d_in[10];
    const float* w1s  = (const float*)d_in[11];
    const float* w2s  = (const float*)d_in[12];
    const float* n1w  = (const float*)d_in[13];
    const float* n1b  = (const float*)d_in[14];
    const float* n2w  = (const float*)d_in[15];
    const float* n2b  = (const float*)d_in[16];
    float* out = (float*)d_out;

    float *p_xn, *p_q, *p_k, *p_v, *p_attn, *p_x1, *p_xm, *p_xs, *p_h1, *p_ht, *p_hs;
    cudaGetSymbolAddress((void**)&p_xn,  g_xn);
    cudaGetSymbolAddress((void**)&p_q,   g_q);
    cudaGetSymbolAddress((void**)&p_k,   g_k);
    cudaGetSymbolAddress((void**)&p_v,   g_v);
    cudaGetSymbolAddress((void**)&p_attn,g_attn);
    cudaGetSymbolAddress((void**)&p_x1,  g_x1);
    cudaGetSymbolAddress((void**)&p_xm,  g_xm);
    cudaGetSymbolAddress((void**)&p_xs,  g_xs);
    cudaGetSymbolAddress((void**)&p_h1,  g_h1);
    cudaGetSymbolAddress((void**)&p_ht,  g_ht);
    cudaGetSymbolAddress((void**)&p_hs,  g_hs);

    decode_mask_kernel<<<1, 256>>>(tmsk);

    // ---- attention path ----
    mink_norm_kernel<<<NROWS, 256>>>(x, n1w, n1b, p_xn);

    dim3 gQKV(DIM / 64, NROWS / 64);
    sgemm_nt<0><<<gQKV, 256>>>(p_xn, Wq, p_q, nullptr, NROWS, DIM, DIM, 1.f, 0);
    sgemm_nt<0><<<gQKV, 256>>>(p_xn, Wk, p_k, nullptr, NROWS, DIM, DIM, 1.f, 0);
    sgemm_nt<0><<<gQKV, 256>>>(p_xn, Wv, p_v, nullptr, NROWS, DIM, DIM, 1.f, 0);

    qeff_kernel<<<(NROWS * NHEAD * 32) / 256, 256>>>(p_q);

    cudaFuncSetAttribute(flash_attn_kernel,
                         cudaFuncAttributeMaxDynamicSharedMemorySize, FA_SMEM);
    flash_attn_kernel<<<32 * 24, 256, FA_SMEM>>>(p_q, p_k, p_v, p_attn);

    // x1 = x + attn @ Wo^T
    sgemm_nt<0><<<gQKV, 256>>>(p_attn, Wo, p_x1, x, NROWS, DIM, DIM, 1.f, 0);

    // ---- FFN path ----
    mink_norm_kernel<<<NROWS, 256>>>(p_x1, n2w, n2b, p_xn);
    apply_mask_kernel<<<(NROWS * DIM / 4) / 256, 256>>>(p_xn, p_xm, p_xs);

    sgemm_nt<1><<<dim3(DFF  / 64, NROWS / 64), 256>>>(p_xn, w1,  p_h1, nullptr, NROWS, DFF,  DIM, 1.f, 0);
    sgemm_nt<2><<<dim3(DFFH / 64, NROWS / 64), 256>>>(p_xm, w1t, p_ht, nullptr, NROWS, DFFH, DIM, 1.f, 0);
    sgemm_nt<1><<<dim3(DFFH / 64, NROWS / 64), 256>>>(p_xs, w1s, p_hs, nullptr, NROWS, DFFH, DIM, 1.f, 0);

    // out = x1 + 0.5*h1@w2^T + 0.5*ht@w2t^T + 0.5*hs@w2s^T
    sgemm_nt<0><<<gQKV, 256>>>(p_h1, w2,  out, p_x1,   NROWS, DIM, DFF,  0.5f, 0);
    sgemm_nt<0><<<gQKV, 256>>>(p_ht, w2t, out, nullptr, NROWS, DIM, DFFH, 0.5f, 1);
    sgemm_nt<0><<<gQKV, 256>>>(p_hs, w2s, out, nullptr, NROWS, DIM, DFFH, 0.5f, 1);
}

// round 4
// speedup vs baseline: 1.0014x; 1.0014x over previous
#include <cuda_runtime.h>
#include <cuda_bf16.h>
#include <math.h>

// Problem constants
#define BATCH 2
#define SEQL  2048
#define DIM   768
#define NHEAD 12
#define DHEAD 64
#define DFF   3072
#define DFFH  1536
#define NROWS (BATCH*SEQL)          // 4096

// ---------------- scratch (static device globals; no allocation) ----------------
__device__ float g_mask[DIM];
__device__ float g_xn [NROWS*DIM];
__device__ float g_q  [NROWS*DIM];
__device__ float g_k  [NROWS*DIM];
__device__ float g_v  [NROWS*DIM];
__device__ float g_attn[NROWS*DIM];
__device__ float g_x1 [NROWS*DIM];
__device__ float g_xm [NROWS*DIM];
__device__ float g_xs [NROWS*DIM];
__device__ float g_h1 [NROWS*DFF];
__device__ float g_ht [NROWS*DFFH];
__device__ float g_hs [NROWS*DFFH];

// ---------------- helpers ----------------
__device__ __forceinline__ float gelu_f(float x) {
    return 0.5f * x * (1.f + erff(x * 0.70710678118654752f));
}
__device__ __forceinline__ float silu_f(float x) {
    return x / (1.f + expf(-x));
}

// ---------------- timelike_mask decode (dtype-robust: f32 / i32 / bool8) ----------------
__global__ void decode_mask_kernel(const void* __restrict__ raw) {
    __shared__ int cls;  // 0=float32, 1=int32, 2=byte
    if (threadIdx.x == 0) {
        const unsigned* w = (const unsigned*)raw;
        int isFloat = 0, isByte = 0;
        for (int i = 0; i < 192; i++) {       // 192 words is safe for every interpretation
            unsigned v = w[i];
            if (v == 0x3F800000u) isFloat = 1;
            if (v != 0u) {
                bool bytes01 = true, hi = false;
                for (int b = 0; b < 4; b++) {
                    unsigned by = (v >> (8*b)) & 0xffu;
                    if (by > 1u) bytes01 = false;
                    if (b > 0 && by) hi = true;
                }
                if (bytes01 && hi) isByte = 1;
            }
        }
        cls = isFloat ? 0 : (isByte ? 2 : 1);
    }
    __syncthreads();
    int c = cls;
    for (int i = threadIdx.x; i < DIM; i += blockDim.x) {
        float mv;
        if (c == 0)      mv = ((const float*)raw)[i];
        else if (c == 1) mv = (float)(((const int*)raw)[i] != 0);
        else             mv = (float)(((const unsigned char*)raw)[i] != 0);
        g_mask[i] = mv;
    }
}

// ---------------- Minkowski LayerNorm: one block (256 thr) per row ----------------
__global__ __launch_bounds__(256) void mink_norm_kernel(
    const float* __restrict__ x, const float* __restrict__ w,
    const float* __restrict__ bb, float* __restrict__ out)
{
    __shared__ float sA[8], sB[8];
    int row = blockIdx.x, t = threadIdx.x;
    const float* xr = x + (size_t)row * DIM;
    float v0 = xr[t], v1 = xr[t+256], v2 = xr[t+512];
    int lane = t & 31, wp = t >> 5;

    float s = v0 + v1 + v2;
    #pragma unroll
    for (int o = 16; o; o >>= 1) s += __shfl_xor_sync(0xffffffffu, s, o);
    if (!lane) sA[wp] = s;
    __syncthreads();
    float tot = 0.f;
    #pragma unroll
    for (int i = 0; i < 8; i++) tot += sA[i];
    float mean = tot * (1.f / DIM);

    float c0 = v0 - mean, c1 = v1 - mean, c2 = v2 - mean;
    float m0 = g_mask[t], m1 = g_mask[t+256], m2 = g_mask[t+512];
    float s2  = c0*c0 + c1*c1 + c2*c2;
    float s2m = c0*c0*m0 + c1*c1*m1 + c2*c2*m2;
    #pragma unroll
    for (int o = 16; o; o >>= 1) {
        s2  += __shfl_xor_sync(0xffffffffu, s2,  o);
        s2m += __shfl_xor_sync(0xffffffffu, s2m, o);
    }
    __syncthreads();
    if (!lane) { sA[wp] = s2; sB[wp] = s2m; }
    __syncthreads();
    float S2 = 0.f, S2m = 0.f;
    #pragma unroll
    for (int i = 0; i < 8; i++) { S2 += sA[i]; S2m += sB[i]; }

    float var = S2 * (1.f / DIM);
    float eta = S2 - 2.f * S2m;     // sum(sq*(1-m)) - sum(sq*m)
    float kk  = 0.5f * (rsqrtf(var + 1e-5f) + rsqrtf(fabsf(eta) + 1e-5f));

    size_t o0 = (size_t)row * DIM + t;
    out[o0]       = w[t]     * (c0 * kk) + bb[t];
    out[o0 + 256] = w[t+256] * (c1 * kk) + bb[t+256];
    out[o0 + 512] = w[t+512] * (c2 * kk) + bb[t+512];
}

// ---------------- generic NT SGEMM: C = ep(alpha, A(MxK) @ B(NxK)^T) ----------------
// ACT: 0 none, 1 gelu(exact), 2 silu.  act applied BEFORE alpha.
// resid != null  -> += resid ;  accumulate -> += existing C
template<int ACT>
__global__ __launch_bounds__(256) void sgemm_nt(
    const float* __restrict__ A, const float* __restrict__ B,
    float* __restrict__ C, const float* __restrict__ resid,
    int M, int N, int K, float alpha, int accumulate)
{
    __shared__ float As[16][68];
    __shared__ float Bs[16][68];
    int tid = threadIdx.x;
    int tx = tid & 15, ty = tid >> 4;
    int bm = blockIdx.y * 64, bn = blockIdx.x * 64;
    int lrow = tid >> 2;            // 0..63
    int lk   = (tid & 3) << 2;      // 0,4,8,12

    const float* Ap = A + (size_t)(bm + lrow) * K + lk;
    const float* Bp = B + (size_t)(bn + lrow) * K + lk;

    float acc[4][4] = {};
    int nk = K >> 4;
    for (int kt = 0; kt < nk; kt++) {
        float4 av = *(const float4*)Ap;
        float4 bv = *(const float4*)Bp;
        As[lk+0][lrow] = av.x; As[lk+1][lrow] = av.y;
        As[lk+2][lrow] = av.z; As[lk+3][lrow] = av.w;
        Bs[lk+0][lrow] = bv.x; Bs[lk+1][lrow] = bv.y;
        Bs[lk+2][lrow] = bv.z; Bs[lk+3][lrow] = bv.w;
        __syncthreads();
        #pragma unroll
        for (int k = 0; k < 16; k++) {
            float4 a = *(const float4*)&As[k][ty << 2];
            float4 b = *(const float4*)&Bs[k][tx << 2];
            float ar[4] = {a.x, a.y, a.z, a.w};
            float br[4] = {b.x, b.y, b.z, b.w};
            #pragma unroll
            for (int i = 0; i < 4; i++)
                #pragma unroll
                for (int j = 0; j < 4; j++)
                    acc[i][j] += ar[i] * br[j];
        }
        __syncthreads();
        Ap += 16; Bp += 16;
    }

    #pragma unroll
    for (int i = 0; i < 4; i++) {
        size_t r = (size_t)(bm + (ty << 2) + i) * N + bn + (tx << 2);
        float vv[4];
        #pragma unroll
        for (int j = 0; j < 4; j++) {
            float t = acc[i][j];
            if (ACT == 1) t = gelu_f(t);
            else if (ACT == 2) t = silu_f(t);
            vv[j] = t * alpha;
        }
        if (resid) {
            float4 rv = *(const float4*)(resid + r);
            vv[0] += rv.x; vv[1] += rv.y; vv[2] += rv.z; vv[3] += rv.w;
        }
        if (accumulate) {
            float4 cv = *(const float4*)(C + r);
            vv[0] += cv.x; vv[1] += cv.y; vv[2] += cv.z; vv[3] += cv.w;
        }
        *(float4*)(C + r) = make_float4(vv[0], vv[1], vv[2], vv[3]);
    }
}

// ---------------- fold Lorentz sf into Q:  Qeff = Q * (1 - 0.5*sf*m) ----------------
__global__ __launch_bounds__(256) void qeff_kernel(float* __restrict__ q)
{
    int gw   = (blockIdx.x * blockDim.x + threadIdx.x) >> 5;
    int lane = threadIdx.x & 31;
    if (gw >= NROWS * NHEAD) return;
    int row = gw / NHEAD, h = gw % NHEAD;
    float* qp = q + (size_t)row * DIM + h * DHEAD;
    float a = qp[lane], c = qp[lane + 32];
    float ma = g_mask[h * DHEAD + lane], mc = g_mask[h * DHEAD + lane + 32];
    float qn2  = a*a + c*c;
    float qtn2 = a*a*ma + c*c*mc;
    #pragma unroll
    for (int o = 16; o; o >>= 1) {
        qn2  += __shfl_xor_sync(0xffffffffu, qn2,  o);
        qtn2 += __shfl_xor_sync(0xffffffffu, qtn2, o);
    }
    float qtn = sqrtf(qtn2);
    float sf  = (qtn > 1e-6f) ? sqrtf(qn2) / fmaxf(qtn, 1e-8f) : 0.f;
    qp[lane]      = a * (1.f - 0.5f * sf * ma);
    qp[lane + 32] = c * (1.f - 0.5f * sf * mc);
}

// ---------------- causal flash attention, fp32, 64x64 tiles ----------------
#define FA_STRIDE 68
#define FA_SMEM   (3 * 64 * FA_STRIDE * 4)

__device__ __forceinline__ void load_tile_T(float* dst, const float* src, int tid) {
    #pragma unroll
    for (int it = 0; it < 4; it++) {
        int idx = tid + it * 256;
        int r = idx >> 4;
        int d4 = (idx & 15) << 2;
        float4 v = *(const float4*)(src + (size_t)r * DIM + d4);
        dst[(d4+0)*FA_STRIDE + r] = v.x; dst[(d4+1)*FA_STRIDE + r] = v.y;
        dst[(d4+2)*FA_STRIDE + r] = v.z; dst[(d4+3)*FA_STRIDE + r] = v.w;
    }
}
__device__ __forceinline__ void load_tile_R(float* dst, const float* src, int tid) {
    #pragma unroll
    for (int it = 0; it < 4; it++) {
        int idx = tid + it * 256;
        int r = idx >> 4;
        int d4 = (idx & 15) << 2;
        *(float4*)(dst + r * FA_STRIDE + d4) = *(const float4*)(src + (size_t)r * DIM + d4);
    }
}

__global__ __launch_bounds__(256) void flash_attn_kernel(
    const float* __restrict__ Q, const float* __restrict__ K,
    const float* __restrict__ V, float* __restrict__ O)
{
    extern __shared__ float sm[];
    float* Qt   = sm;                        // [64 d][68]: Qt[d][i]
    float* KtPt = sm + 64 * FA_STRIDE;       // Kt[d][j]  then Pt[j][i]
    float* Vs   = sm + 2 * 64 * FA_STRIDE;   // Vs[j][d]

    int tid = threadIdx.x;
    int tx = tid & 15, ty = tid >> 4;
    int bid = blockIdx.x;
    int qt = 31 - bid / 24;                  // long blocks first
    int bh = bid % 24;
    int b = bh / NHEAD, h = bh % NHEAD;
    const size_t head_off = (size_t)b * SEQL * DIM + (size_t)h * DHEAD;

    load_tile_T(Qt, Q + head_off + (size_t)qt * 64 * DIM, tid);

    float acc[4][4] = {};
    float mrun[4] = {-1e30f, -1e30f, -1e30f, -1e30f};
    float lrun[4] = {};

    for (int kt = 0; kt <= qt; kt++) {
        load_tile_T(KtPt, K + head_off + (size_t)kt * 64 * DIM, tid);
        load_tile_R(Vs,   V + head_off + (size_t)kt * 64 * DIM, tid);
        __syncthreads();

        float s[4][4] = {};
        #pragma unroll 16
        for (int d = 0; d < 64; d++) {
            float4 a = *(const float4*)&Qt[d * FA_STRIDE + (ty << 2)];
            float4 bb = *(const float4*)&KtPt[d * FA_STRIDE + (tx << 2)];
            float ar[4] = {a.x, a.y, a.z, a.w};
            float br[4] = {bb.x, bb.y, bb.z, bb.w};
            #pragma unroll
            for (int i = 0; i < 4; i++)
                #pragma unroll
                for (int j = 0; j < 4; j++)
                    s[i][j] += ar[i] * br[j];
        }
        #pragma unroll
        for (int i = 0; i < 4; i++)
            #pragma unroll
            for (int j = 0; j < 4; j++)
                s[i][j] *= 0.125f;                     // 1/sqrt(64)

        if (kt == qt) {
            #pragma unroll
            for (int i = 0; i < 4; i++)
                #pragma unroll
                for (int j = 0; j < 4; j++)
                    if ((tx << 2) + j > (ty << 2) + i) s[i][j] = -1e30f;
        }

        #pragma unroll
        for (int i = 0; i < 4; i++) {
            float rm = fmaxf(fmaxf(s[i][0], s[i][1]), fmaxf(s[i][2], s[i][3]));
            #pragma unroll
            for (int o = 8; o; o >>= 1)
                rm = fmaxf(rm, __shfl_xor_sync(0xffffffffu, rm, o));
            float mn = fmaxf(mrun[i], rm);
            float sc = __expf(mrun[i] - mn);
            float rs = 0.f;
            #pragma unroll
            for (int j = 0; j < 4; j++) { s[i][j] = __expf(s[i][j] - mn); rs += s[i][j]; }
            #pragma unroll
            for (int o = 8; o; o >>= 1)
                rs += __shfl_xor_sync(0xffffffffu, rs, o);
            lrun[i] = lrun[i] * sc + rs;
            mrun[i] = mn;
            #pragma unroll
            for (int j = 0; j < 4; j++) acc[i][j] *= sc;
        }

        __syncthreads();   // everyone done reading Kt
        #pragma unroll
        for (int i = 0; i < 4; i++)
            #pragma unroll
            for (int j = 0; j < 4; j++)
                KtPt[((tx << 2) + j) * FA_STRIDE + (ty << 2) + i] = s[i][j];
        __syncthreads();   // P visible

        #pragma unroll 16
        for (int j = 0; j < 64; j++) {
            float4 p  = *(const float4*)&KtPt[j * FA_STRIDE + (ty << 2)];
            float4 vv = *(const float4*)&Vs[j * FA_STRIDE + (tx << 2)];
            float pr[4] = {p.x, p.y, p.z, p.w};
            float vr[4] = {vv.x, vv.y, vv.z, vv.w};
            #pragma unroll
            for (int i = 0; i < 4; i++)
                #pragma unroll
                for (int d = 0; d < 4; d++)
                    acc[i][d] += pr[i] * vr[d];
        }
        __syncthreads();   // done reading before next tile overwrite
    }

    #pragma unroll
    for (int i = 0; i < 4; i++) {
        float inv = 1.f / lrun[i];
        size_t row = (size_t)b * SEQL + qt * 64 + (ty << 2) + i;
        *(float4*)(O + row * DIM + h * DHEAD + (tx << 2)) =
            make_float4(acc[i][0]*inv, acc[i][1]*inv, acc[i][2]*inv, acc[i][3]*inv);
    }
}

// ---------------- elementwise masked splits for FFN ----------------
__global__ __launch_bounds__(256) void apply_mask_kernel(
    const float* __restrict__ xn, float* __restrict__ xm, float* __restrict__ xs)
{
    int i = blockIdx.x * blockDim.x + threadIdx.x;       // float4 index
    float4 v = ((const float4*)xn)[i];
    int col = (i % (DIM / 4)) * 4;
    float m0 = g_mask[col], m1 = g_mask[col+1], m2 = g_mask[col+2], m3 = g_mask[col+3];
    ((float4*)xm)[i] = make_float4(v.x*m0, v.y*m1, v.z*m2, v.w*m3);
    ((float4*)xs)[i] = make_float4(v.x*(1.f-m0), v.y*(1.f-m1), v.z*(1.f-m2), v.w*(1.f-m3));
}

// ---------------- host launcher ----------------
extern "C" void kernel_launch(void* const* d_in, const int* in_sizes, int n_in,
                              void* d_out, int out_size)
{
    const float* x    = (const float*)d_in[0];
    const void*  tmsk = d_in[2];
    const float* Wq   = (const float*)d_in[3];
    const float* Wk   = (const float*)d_in[4];
    const float* Wv   = (const float*)d_in[5];
    const float* Wo   = (const float*)d_in[6];
    const float* w1   = (const float*)d_in[7];
    const float* w2   = (const float*)d_in[8];
    const float* w1t  = (const float*)d_in[9];
    const float* w2t  = (const float*)d_in[10];
    const float* w1s  = (const float*)d_in[11];
    const float* w2s  = (const float*)d_in[12];
    const float* n1w  = (const float*)d_in[13];
    const float* n1b  = (const float*)d_in[14];
    const float* n2w  = (const float*)d_in[15];
    const float* n2b  = (const float*)d_in[16];
    float* out = (float*)d_out;

    float *p_xn, *p_q, *p_k, *p_v, *p_attn, *p_x1, *p_xm, *p_xs, *p_h1, *p_ht, *p_hs;
    cudaGetSymbolAddress((void**)&p_xn,  g_xn);
    cudaGetSymbolAddress((void**)&p_q,   g_q);
    cudaGetSymbolAddress((void**)&p_k,   g_k);
    cudaGetSymbolAddress((void**)&p_v,   g_v);
    cudaGetSymbolAddress((void**)&p_attn,g_attn);
    cudaGetSymbolAddress((void**)&p_x1,  g_x1);
    cudaGetSymbolAddress((void**)&p_xm,  g_xm);
    cudaGetSymbolAddress((void**)&p_xs,  g_xs);
    cudaGetSymbolAddress((void**)&p_h1,  g_h1);
    cudaGetSymbolAddress((void**)&p_ht,  g_ht);
    cudaGetSymbolAddress((void**)&p_hs,  g_hs);

    decode_mask_kernel<<<1, 256>>>(tmsk);

    // ---- attention path ----
    mink_norm_kernel<<<NROWS, 256>>>(x, n1w, n1b, p_xn);

    dim3 gQKV(DIM / 64, NROWS / 64);
    sgemm_nt<0><<<gQKV, 256>>>(p_xn, Wq, p_q, nullptr, NROWS, DIM, DIM, 1.f, 0);
    sgemm_nt<0><<<gQKV, 256>>>(p_xn, Wk, p_k, nullptr, NROWS, DIM, DIM, 1.f, 0);
    sgemm_nt<0><<<gQKV, 256>>>(p_xn, Wv, p_v, nullptr, NROWS, DIM, DIM, 1.f, 0);

    qeff_kernel<<<(NROWS * NHEAD * 32) / 256, 256>>>(p_q);

    cudaFuncSetAttribute(flash_attn_kernel,
                         cudaFuncAttributeMaxDynamicSharedMemorySize, FA_SMEM);
    flash_attn_kernel<<<32 * 24, 256, FA_SMEM>>>(p_q, p_k, p_v, p_attn);

    // x1 = x + attn @ Wo^T
    sgemm_nt<0><<<gQKV, 256>>>(p_attn, Wo, p_x1, x, NROWS, DIM, DIM, 1.f, 0);

    // ---- FFN path ----
    mink_norm_kernel<<<NROWS, 256>>>(p_x1, n2w, n2b, p_xn);
    apply_mask_kernel<<<(NROWS * DIM / 4) / 256, 256>>>(p_xn, p_xm, p_xs);

    sgemm_nt<1><<<dim3(DFF  / 64, NROWS / 64), 256>>>(p_xn, w1,  p_h1, nullptr, NROWS, DFF,  DIM, 1.f, 0);
    sgemm_nt<2><<<dim3(DFFH / 64, NROWS / 64), 256>>>(p_xm, w1t, p_ht, nullptr, NROWS, DFFH, DIM, 1.f, 0);
    sgemm_nt<1><<<dim3(DFFH / 64, NROWS / 64), 256>>>(p_xs, w1s, p_hs, nullptr, NROWS, DFFH, DIM, 1.f, 0);

    // out = x1 + 0.5*h1@w2^T + 0.5*ht@w2t^T + 0.5*hs@w2s^T
    sgemm_nt<0><<<gQKV, 256>>>(p_h1, w2,  out, p_x1,   NROWS, DIM, DFF,  0.5f, 0);
    sgemm_nt<0><<<gQKV, 256>>>(p_ht, w2t, out, nullptr, NROWS, DIM, DFFH, 0.5f, 1);
    sgemm_nt<0><<<gQKV, 256>>>(p_hs, w2s, out, nullptr, NROWS, DIM, DFFH, 0.5f, 1);
}

// round 5
// speedup vs baseline: 2.7039x; 2.7001x over previous
#include <cuda_runtime.h>
#include <math.h>

// Problem constants
#define BATCH 2
#define SEQL  2048
#define DIM   768
#define NHEAD 12
#define DHEAD 64
#define DFF   3072
#define DFFH  1536
#define NROWS (BATCH*SEQL)          // 4096
#define QKVLD 2304                  // concat QKV row stride
#define KCAT  6144                  // concat FFN hidden width

// ---------------- scratch (static device globals; no allocation) ----------------
__device__ float g_mask[DIM];
__device__ float g_xn  [NROWS*DIM];
__device__ float g_qkv [(size_t)NROWS*QKVLD];
__device__ float g_attn[NROWS*DIM];
__device__ float g_x1  [NROWS*DIM];
__device__ float g_xm  [NROWS*DIM];
__device__ float g_xs  [NROWS*DIM];
__device__ float g_hcat[(size_t)NROWS*KCAT];
__device__ float g_wqkv[QKVLD*DIM];
__device__ float g_w2cat[DIM*KCAT];

// ---------------- helpers ----------------
__device__ __forceinline__ float gelu_f(float x) {
    return 0.5f * x * (1.f + erff(x * 0.70710678118654752f));
}
__device__ __forceinline__ float silu_f(float x) {
    return x / (1.f + expf(-x));
}
__device__ __forceinline__ unsigned f2tf(float f) {
    unsigned u; asm("cvt.rna.tf32.f32 %0, %1;" : "=r"(u) : "f"(f)); return u;
}
__device__ __forceinline__ float tf(float f) { return __uint_as_float(f2tf(f)); }

// m16n8k8 tf32 mma: D += A(16x8 row) * B(8x8 col)
__device__ __forceinline__ void mma8(float* c, const unsigned* a, const unsigned* b) {
    asm volatile(
        "mma.sync.aligned.m16n8k8.row.col.f32.tf32.tf32.f32 "
        "{%0,%1,%2,%3}, {%4,%5,%6,%7}, {%8,%9}, {%0,%1,%2,%3};\n"
        : "+f"(c[0]), "+f"(c[1]), "+f"(c[2]), "+f"(c[3])
        : "r"(a[0]), "r"(a[1]), "r"(a[2]), "r"(a[3]), "r"(b[0]), "r"(b[1]));
}

// ---------------- timelike_mask decode (dtype-robust: f32 / i32 / bool8) ----------------
__global__ void decode_mask_kernel(const void* __restrict__ raw) {
    __shared__ int cls;
    if (threadIdx.x == 0) {
        const unsigned* w = (const unsigned*)raw;
        int isFloat = 0, isByte = 0;
        for (int i = 0; i < 192; i++) {
            unsigned v = w[i];
            if (v == 0x3F800000u) isFloat = 1;
            if (v != 0u) {
                bool bytes01 = true, hi = false;
                for (int b = 0; b < 4; b++) {
                    unsigned by = (v >> (8*b)) & 0xffu;
                    if (by > 1u) bytes01 = false;
                    if (b > 0 && by) hi = true;
                }
                if (bytes01 && hi) isByte = 1;
            }
        }
        cls = isFloat ? 0 : (isByte ? 2 : 1);
    }
    __syncthreads();
    int c = cls;
    for (int i = threadIdx.x; i < DIM; i += blockDim.x) {
        float mv;
        if (c == 0)      mv = ((const float*)raw)[i];
        else if (c == 1) mv = (float)(((const int*)raw)[i] != 0);
        else             mv = (float)(((const unsigned char*)raw)[i] != 0);
        g_mask[i] = mv;
    }
}

// ---------------- Minkowski LayerNorm: one block (256 thr) per row ----------------
__global__ __launch_bounds__(256) void mink_norm_kernel(
    const float* __restrict__ x, const float* __restrict__ w,
    const float* __restrict__ bb, float* __restrict__ out)
{
    __shared__ float sA[8], sB[8];
    int row = blockIdx.x, t = threadIdx.x;
    const float* xr = x + (size_t)row * DIM;
    float v0 = xr[t], v1 = xr[t+256], v2 = xr[t+512];
    int lane = t & 31, wp = t >> 5;

    float s = v0 + v1 + v2;
    #pragma unroll
    for (int o = 16; o; o >>= 1) s += __shfl_xor_sync(0xffffffffu, s, o);
    if (!lane) sA[wp] = s;
    __syncthreads();
    float tot = 0.f;
    #pragma unroll
    for (int i = 0; i < 8; i++) tot += sA[i];
    float mean = tot * (1.f / DIM);

    float c0 = v0 - mean, c1 = v1 - mean, c2 = v2 - mean;
    float m0 = g_mask[t], m1 = g_mask[t+256], m2 = g_mask[t+512];
    float s2  = c0*c0 + c1*c1 + c2*c2;
    float s2m = c0*c0*m0 + c1*c1*m1 + c2*c2*m2;
    #pragma unroll
    for (int o = 16; o; o >>= 1) {
        s2  += __shfl_xor_sync(0xffffffffu, s2,  o);
        s2m += __shfl_xor_sync(0xffffffffu, s2m, o);
    }
    __syncthreads();
    if (!lane) { sA[wp] = s2; sB[wp] = s2m; }
    __syncthreads();
    float S2 = 0.f, S2m = 0.f;
    #pragma unroll
    for (int i = 0; i < 8; i++) { S2 += sA[i]; S2m += sB[i]; }

    float var = S2 * (1.f / DIM);
    float eta = S2 - 2.f * S2m;
    float kk  = 0.5f * (rsqrtf(var + 1e-5f) + rsqrtf(fabsf(eta) + 1e-5f));

    size_t o0 = (size_t)row * DIM + t;
    out[o0]       = w[t]     * (c0 * kk) + bb[t];
    out[o0 + 256] = w[t+256] * (c1 * kk) + bb[t+256];
    out[o0 + 512] = w[t+512] * (c2 * kk) + bb[t+512];
}

// ---------------- tf32 tensor-core NT GEMM ----------------
// C[M,N] = ep(alpha, act(A[M,K] @ B[N,K]^T)) (+ resid), C row stride ldc.
// ACT: 0 none, 1 gelu(exact), 2 silu (act applied before alpha).
#define BM 128
#define BN 128
#define BK 16
#define ASTR 20   // smem row stride in words (conflict-free for frag loads)

template<int ACT>
__global__ __launch_bounds__(256, 2) void tgemm(
    const float* __restrict__ A, const float* __restrict__ B,
    float* __restrict__ C, const float* __restrict__ resid,
    int K, int ldc, float alpha)
{
    __shared__ unsigned As[2][BM*ASTR];
    __shared__ unsigned Bs[2][BN*ASTR];

    int tid = threadIdx.x, lane = tid & 31, wid = tid >> 5;
    int wm = wid & 1, wn = wid >> 1;          // 2 x 4 warp grid
    int g = lane >> 2, t = lane & 3;
    int bm = blockIdx.y * BM, bn = blockIdx.x * BN;

    int lr = tid >> 2;                        // 0..63
    int lk = (tid & 3) << 2;                  // 0,4,8,12
    const float* Ap = A + (size_t)(bm + lr) * K + lk;
    const float* Bp = B + (size_t)(bn + lr) * K + lk;

    // preload tile 0
    float4 a0v = *(const float4*)Ap;
    float4 a1v = *(const float4*)(Ap + (size_t)64 * K);
    float4 b0v = *(const float4*)Bp;
    float4 b1v = *(const float4*)(Bp + (size_t)64 * K);
    {
        uint4 u;
        u = make_uint4(f2tf(a0v.x), f2tf(a0v.y), f2tf(a0v.z), f2tf(a0v.w));
        *(uint4*)&As[0][lr*ASTR + lk] = u;
        u = make_uint4(f2tf(a1v.x), f2tf(a1v.y), f2tf(a1v.z), f2tf(a1v.w));
        *(uint4*)&As[0][(lr+64)*ASTR + lk] = u;
        u = make_uint4(f2tf(b0v.x), f2tf(b0v.y), f2tf(b0v.z), f2tf(b0v.w));
        *(uint4*)&Bs[0][lr*ASTR + lk] = u;
        u = make_uint4(f2tf(b1v.x), f2tf(b1v.y), f2tf(b1v.z), f2tf(b1v.w));
        *(uint4*)&Bs[0][(lr+64)*ASTR + lk] = u;
    }
    __syncthreads();

    float acc[4][4][4] = {};
    int nk = K / BK;
    for (int kt = 0; kt < nk; kt++) {
        int cur = kt & 1;
        bool more = (kt + 1 < nk);
        if (more) {
            Ap += BK; Bp += BK;
            a0v = *(const float4*)Ap;
            a1v = *(const float4*)(Ap + (size_t)64 * K);
            b0v = *(const float4*)Bp;
            b1v = *(const float4*)(Bp + (size_t)64 * K);
        }
        const unsigned* Ab = As[cur];
        const unsigned* Bb = Bs[cur];
        #pragma unroll
        for (int k8 = 0; k8 < BK; k8 += 8) {
            unsigned af[4][4], bf[4][2];
            #pragma unroll
            for (int mt = 0; mt < 4; mt++) {
                const unsigned* p = &Ab[(wm*64 + mt*16 + g)*ASTR + k8 + t];
                af[mt][0] = p[0];
                af[mt][1] = p[8*ASTR];
                af[mt][2] = p[4];
                af[mt][3] = p[8*ASTR + 4];
            }
            #pragma unroll
            for (int nt = 0; nt < 4; nt++) {
                const unsigned* p = &Bb[(wn*32 + nt*8 + g)*ASTR + k8 + t];
                bf[nt][0] = p[0];
                bf[nt][1] = p[4];
            }
            #pragma unroll
            for (int mt = 0; mt < 4; mt++)
                #pragma unroll
                for (int nt = 0; nt < 4; nt++)
                    mma8(acc[mt][nt], af[mt], bf[nt]);
        }
        if (more) {
            int nxt = cur ^ 1;
            uint4 u;
            u = make_uint4(f2tf(a0v.x), f2tf(a0v.y), f2tf(a0v.z), f2tf(a0v.w));
            *(uint4*)&As[nxt][lr*ASTR + lk] = u;
            u = make_uint4(f2tf(a1v.x), f2tf(a1v.y), f2tf(a1v.z), f2tf(a1v.w));
            *(uint4*)&As[nxt][(lr+64)*ASTR + lk] = u;
            u = make_uint4(f2tf(b0v.x), f2tf(b0v.y), f2tf(b0v.z), f2tf(b0v.w));
            *(uint4*)&Bs[nxt][lr*ASTR + lk] = u;
            u = make_uint4(f2tf(b1v.x), f2tf(b1v.y), f2tf(b1v.z), f2tf(b1v.w));
            *(uint4*)&Bs[nxt][(lr+64)*ASTR + lk] = u;
        }
        __syncthreads();
    }

    // epilogue
    #pragma unroll
    for (int mt = 0; mt < 4; mt++) {
        int r0 = bm + wm*64 + mt*16 + g;
        #pragma unroll
        for (int nt = 0; nt < 4; nt++) {
            int c = bn + wn*32 + nt*8 + (t << 1);
            #pragma unroll
            for (int hh = 0; hh < 2; hh++) {
                float v0 = acc[mt][nt][2*hh];
                float v1 = acc[mt][nt][2*hh + 1];
                if (ACT == 1) { v0 = gelu_f(v0); v1 = gelu_f(v1); }
                else if (ACT == 2) { v0 = silu_f(v0); v1 = silu_f(v1); }
                v0 *= alpha; v1 *= alpha;
                size_t idx = (size_t)(r0 + 8*hh) * ldc + c;
                if (resid) {
                    float2 rv = *(const float2*)(resid + idx);
                    v0 += rv.x; v1 += rv.y;
                }
                *(float2*)(C + idx) = make_float2(v0, v1);
            }
        }
    }
}

// ---------------- fold Lorentz sf + 1/sqrt(DH) into Q ----------------
__global__ __launch_bounds__(256) void qeff_kernel(float* __restrict__ qkv)
{
    int gw   = (blockIdx.x * blockDim.x + threadIdx.x) >> 5;
    int lane = threadIdx.x & 31;
    if (gw >= NROWS * NHEAD) return;
    int row = gw / NHEAD, h = gw % NHEAD;
    float* qp = qkv + (size_t)row * QKVLD + h * DHEAD;
    float a = qp[lane], c = qp[lane + 32];
    float ma = g_mask[h * DHEAD + lane], mc = g_mask[h * DHEAD + lane + 32];
    float qn2  = a*a + c*c;
    float qtn2 = a*a*ma + c*c*mc;
    #pragma unroll
    for (int o = 16; o; o >>= 1) {
        qn2  += __shfl_xor_sync(0xffffffffu, qn2,  o);
        qtn2 += __shfl_xor_sync(0xffffffffu, qtn2, o);
    }
    float qtn = sqrtf(qtn2);
    float sf  = (qtn > 1e-6f) ? sqrtf(qn2) / fmaxf(qtn, 1e-8f) : 0.f;
    qp[lane]      = a * (1.f - 0.5f * sf * ma) * 0.125f;   // fold 1/sqrt(64)
    qp[lane + 32] = c * (1.f - 0.5f * sf * mc) * 0.125f;
}

// ---------------- tf32 tensor-core causal flash attention ----------------
// BQ=128, BK=64, 256 threads (8 warps, one 16-row m-tile each, full 64 n-cols).
#define FS 68
#define FA_SMEM (384 * FS * 4)

__global__ __launch_bounds__(256) void flash_tc(
    const float* __restrict__ QKV, float* __restrict__ O)
{
    extern __shared__ float sm[];
    float* Qs = sm;                   // [128][FS]  rows i, cols d (tf32)
    float* Ks = sm + 128 * FS;        // [64][FS]   rows j, cols d
    float* Vt = sm + 192 * FS;        // [64][FS]   rows d, cols j (transposed)
    float* Ps = sm + 256 * FS;        // [128][FS]  warp-private P slices

    int tid = threadIdx.x, lane = tid & 31, wid = tid >> 5;
    int g = lane >> 2, t = lane & 3;
    int bid = blockIdx.x;
    int qb = 15 - bid / 24;           // long blocks first
    int bh = bid % 24;
    int b = bh / NHEAD, h = bh % NHEAD;

    const float* Qp = QKV + (size_t)(b * SEQL + qb * 128) * QKVLD + h * DHEAD;
    const float* Kp = QKV + (size_t)(b * SEQL) * QKVLD + DIM + h * DHEAD;
    const float* Vp = Kp + DIM;

    // load Q tile (128x64) row-major, tf32-converted
    #pragma unroll
    for (int it = 0; it < 8; it++) {
        int idx = tid + it * 256;
        int r = idx >> 4, c4 = (idx & 15) << 2;
        float4 v = *(const float4*)(Qp + (size_t)r * QKVLD + c4);
        *(float4*)&Qs[r * FS + c4] = make_float4(tf(v.x), tf(v.y), tf(v.z), tf(v.w));
    }

    float oacc[8][4] = {};
    float mrun[2] = {-1e30f, -1e30f}, lrun[2] = {0.f, 0.f};
    int rbase = qb * 128 + wid * 16;  // this warp's global row base
    int kmax = 2 * qb + 2;

    for (int kt = 0; kt < kmax; kt++) {
        __syncthreads();              // prev Vt/Ks reads done (also covers Qs first time)
        #pragma unroll
        for (int it = 0; it < 4; it++) {
            int idx = tid + it * 256;
            int r = idx >> 4, c4 = (idx & 15) << 2;
            float4 v = *(const float4*)(Kp + (size_t)(kt * 64 + r) * QKVLD + c4);
            *(float4*)&Ks[r * FS + c4] = make_float4(tf(v.x), tf(v.y), tf(v.z), tf(v.w));
            float4 w = *(const float4*)(Vp + (size_t)(kt * 64 + r) * QKVLD + c4);
            Vt[(c4 + 0) * FS + r] = tf(w.x);
            Vt[(c4 + 1) * FS + r] = tf(w.y);
            Vt[(c4 + 2) * FS + r] = tf(w.z);
            Vt[(c4 + 3) * FS + r] = tf(w.w);
        }
        __syncthreads();

        // S = Q @ K^T  (scale pre-folded into Q)
        float s[8][4] = {};
        #pragma unroll
        for (int k8 = 0; k8 < 64; k8 += 8) {
            unsigned aq[4];
            const float* qp2 = &Qs[(wid * 16 + g) * FS + k8 + t];
            aq[0] = __float_as_uint(qp2[0]);
            aq[1] = __float_as_uint(qp2[8 * FS]);
            aq[2] = __float_as_uint(qp2[4]);
            aq[3] = __float_as_uint(qp2[8 * FS + 4]);
            #pragma unroll
            for (int nt = 0; nt < 8; nt++) {
                unsigned bk[2];
                const float* kp2 = &Ks[(nt * 8 + g) * FS + k8 + t];
                bk[0] = __float_as_uint(kp2[0]);
                bk[1] = __float_as_uint(kp2[4]);
                mma8(s[nt], aq, bk);
            }
        }

        // causal mask (only tiles touching/above the diagonal for this warp)
        if (kt * 64 + 63 > rbase) {
            int r0 = rbase + g, r1 = r0 + 8;
            #pragma unroll
            for (int nt = 0; nt < 8; nt++) {
                int c0 = kt * 64 + nt * 8 + t * 2;
                if (c0     > r0) s[nt][0] = -1e30f;
                if (c0 + 1 > r0) s[nt][1] = -1e30f;
                if (c0     > r1) s[nt][2] = -1e30f;
                if (c0 + 1 > r1) s[nt][3] = -1e30f;
            }
        }

        // online softmax (rows g and g+8)
        #pragma unroll
        for (int r = 0; r < 2; r++) {
            float rm = -1e30f;
            #pragma unroll
            for (int nt = 0; nt < 8; nt++)
                rm = fmaxf(rm, fmaxf(s[nt][2*r], s[nt][2*r + 1]));
            rm = fmaxf(rm, __shfl_xor_sync(0xffffffffu, rm, 1));
            rm = fmaxf(rm, __shfl_xor_sync(0xffffffffu, rm, 2));
            float mn = fmaxf(mrun[r], rm);
            float sc = __expf(mrun[r] - mn);
            float rs = 0.f;
            #pragma unroll
            for (int nt = 0; nt < 8; nt++) {
                s[nt][2*r]     = __expf(s[nt][2*r]     - mn);
                s[nt][2*r + 1] = __expf(s[nt][2*r + 1] - mn);
                rs += s[nt][2*r] + s[nt][2*r + 1];
            }
            rs += __shfl_xor_sync(0xffffffffu, rs, 1);
            rs += __shfl_xor_sync(0xffffffffu, rs, 2);
            lrun[r] = lrun[r] * sc + rs;
            mrun[r] = mn;
            #pragma unroll
            for (int nt = 0; nt < 8; nt++) {
                oacc[nt][2*r]     *= sc;
                oacc[nt][2*r + 1] *= sc;
            }
        }

        // stage P (warp-private 16x64 slice), tf32-converted
        #pragma unroll
        for (int nt = 0; nt < 8; nt++) {
            int c = nt * 8 + t * 2;
            Ps[(wid * 16 + g    ) * FS + c    ] = tf(s[nt][0]);
            Ps[(wid * 16 + g    ) * FS + c + 1] = tf(s[nt][1]);
            Ps[(wid * 16 + g + 8) * FS + c    ] = tf(s[nt][2]);
            Ps[(wid * 16 + g + 8) * FS + c + 1] = tf(s[nt][3]);
        }
        __syncwarp();

        // O += P @ V
        #pragma unroll
        for (int k8 = 0; k8 < 64; k8 += 8) {
            unsigned ap[4];
            const float* pp = &Ps[(wid * 16 + g) * FS + k8 + t];
            ap[0] = __float_as_uint(pp[0]);
            ap[1] = __float_as_uint(pp[8 * FS]);
            ap[2] = __float_as_uint(pp[4]);
            ap[3] = __float_as_uint(pp[8 * FS + 4]);
            #pragma unroll
            for (int nt = 0; nt < 8; nt++) {
                unsigned bv[2];
                const float* vp2 = &Vt[(nt * 8 + g) * FS + k8 + t];
                bv[0] = __float_as_uint(vp2[0]);
                bv[1] = __float_as_uint(vp2[4]);
                mma8(oacc[nt], ap, bv);
            }
        }
    }

    float i0 = 1.f / lrun[0], i1 = 1.f / lrun[1];
    size_t grow0 = (size_t)b * SEQL + qb * 128 + wid * 16 + g;
    #pragma unroll
    for (int nt = 0; nt < 8; nt++) {
        int c = h * DHEAD + nt * 8 + t * 2;
        *(float2*)&O[grow0 * DIM + c] =
            make_float2(oacc[nt][0] * i0, oacc[nt][1] * i0);
        *(float2*)&O[(grow0 + 8) * DIM + c] =
            make_float2(oacc[nt][2] * i1, oacc[nt][3] * i1);
    }
}

// ---------------- elementwise masked splits for FFN ----------------
__global__ __launch_bounds__(256) void apply_mask_kernel(
    const float* __restrict__ xn, float* __restrict__ xm, float* __restrict__ xs)
{
    int i = blockIdx.x * blockDim.x + threadIdx.x;       // float4 index
    float4 v = ((const float4*)xn)[i];
    int col = (i % (DIM / 4)) * 4;
    float m0 = g_mask[col], m1 = g_mask[col+1], m2 = g_mask[col+2], m3 = g_mask[col+3];
    ((float4*)xm)[i] = make_float4(v.x*m0, v.y*m1, v.z*m2, v.w*m3);
    ((float4*)xs)[i] = make_float4(v.x*(1.f-m0), v.y*(1.f-m1), v.z*(1.f-m2), v.w*(1.f-m3));
}

// ---------------- host launcher ----------------
extern "C" void kernel_launch(void* const* d_in, const int* in_sizes, int n_in,
                              void* d_out, int out_size)
{
    const float* x    = (const float*)d_in[0];
    const void*  tmsk = d_in[2];
    const float* Wq   = (const float*)d_in[3];
    const float* Wk   = (const float*)d_in[4];
    const float* Wv   = (const float*)d_in[5];
    const float* Wo   = (const float*)d_in[6];
    const float* w1   = (const float*)d_in[7];
    const float* w2   = (const float*)d_in[8];
    const float* w1t  = (const float*)d_in[9];
    const float* w2t  = (const float*)d_in[10];
    const float* w1s  = (const float*)d_in[11];
    const float* w2s  = (const float*)d_in[12];
    const float* n1w  = (const float*)d_in[13];
    const float* n1b  = (const float*)d_in[14];
    const float* n2w  = (const float*)d_in[15];
    const float* n2b  = (const float*)d_in[16];
    float* out = (float*)d_out;

    float *p_xn, *p_qkv, *p_attn, *p_x1, *p_xm, *p_xs, *p_hcat, *p_wqkv, *p_w2cat;
    cudaGetSymbolAddress((void**)&p_xn,    g_xn);
    cudaGetSymbolAddress((void**)&p_qkv,   g_qkv);
    cudaGetSymbolAddress((void**)&p_attn,  g_attn);
    cudaGetSymbolAddress((void**)&p_x1,    g_x1);
    cudaGetSymbolAddress((void**)&p_xm,    g_xm);
    cudaGetSymbolAddress((void**)&p_xs,    g_xs);
    cudaGetSymbolAddress((void**)&p_hcat,  g_hcat);
    cudaGetSymbolAddress((void**)&p_wqkv,  g_wqkv);
    cudaGetSymbolAddress((void**)&p_w2cat, g_w2cat);

    decode_mask_kernel<<<1, 256>>>(tmsk);

    // concat Wq/Wk/Wv -> [2304, 768] (contiguous copies)
    size_t wsz = (size_t)DIM * DIM * sizeof(float);
    cudaMemcpyAsync(p_wqkv,             Wq, wsz, cudaMemcpyDeviceToDevice, 0);
    cudaMemcpyAsync(p_wqkv + DIM*DIM,   Wk, wsz, cudaMemcpyDeviceToDevice, 0);
    cudaMemcpyAsync(p_wqkv + 2*DIM*DIM, Wv, wsz, cudaMemcpyDeviceToDevice, 0);
    // concat w2|w2t|w2s along K -> [768, 6144] (strided copies)
    cudaMemcpy2DAsync(p_w2cat,        KCAT*4, w2,  DFF*4,  DFF*4,  DIM,
                      cudaMemcpyDeviceToDevice, 0);
    cudaMemcpy2DAsync(p_w2cat + DFF,  KCAT*4, w2t, DFFH*4, DFFH*4, DIM,
                      cudaMemcpyDeviceToDevice, 0);
    cudaMemcpy2DAsync(p_w2cat + DFF + DFFH, KCAT*4, w2s, DFFH*4, DFFH*4, DIM,
                      cudaMemcpyDeviceToDevice, 0);

    // ---- attention path ----
    mink_norm_kernel<<<NROWS, 256>>>(x, n1w, n1b, p_xn);

    // QKV in one GEMM: [4096,768] x [2304,768]^T -> [4096,2304]
    tgemm<0><<<dim3(QKVLD/BN, NROWS/BM), 256>>>(p_xn, p_wqkv, p_qkv, nullptr,
                                                DIM, QKVLD, 1.f);
    qeff_kernel<<<(NROWS * NHEAD * 32) / 256, 256>>>(p_qkv);

    cudaFuncSetAttribute(flash_tc, cudaFuncAttributeMaxDynamicSharedMemorySize, FA_SMEM);
    flash_tc<<<16 * 24, 256, FA_SMEM>>>(p_qkv, p_attn);

    // x1 = x + attn @ Wo^T
    tgemm<0><<<dim3(DIM/BN, NROWS/BM), 256>>>(p_attn, Wo, p_x1, x, DIM, DIM, 1.f);

    // ---- FFN path ----
    mink_norm_kernel<<<NROWS, 256>>>(p_x1, n2w, n2b, p_xn);
    apply_mask_kernel<<<(NROWS * DIM / 4) / 256, 256>>>(p_xn, p_xm, p_xs);

    // up-projections write into one [4096, 6144] buffer at column offsets
    tgemm<1><<<dim3(DFF /BN, NROWS/BM), 256>>>(p_xn, w1,  p_hcat,              nullptr, DIM, KCAT, 1.f);
    tgemm<2><<<dim3(DFFH/BN, NROWS/BM), 256>>>(p_xm, w1t, p_hcat + DFF,        nullptr, DIM, KCAT, 1.f);
    tgemm<1><<<dim3(DFFH/BN, NROWS/BM), 256>>>(p_xs, w1s, p_hcat + DFF + DFFH, nullptr, DIM, KCAT, 1.f);

    // out = x1 + 0.5 * hcat @ w2cat^T   (single K=6144 GEMM)
    tgemm<0><<<dim3(DIM/BN, NROWS/BM), 256>>>(p_hcat, p_w2cat, out, p_x1,
                                              KCAT, DIM, 0.5f);
}

// round 6
// speedup vs baseline: 2.9775x; 1.1012x over previous
#include <cuda_runtime.h>
#include <math.h>

// Problem constants
#define BATCH 2
#define SEQL  2048
#define DIM   768
#define NHEAD 12
#define DHEAD 64
#define DFF   3072
#define DFFH  1536
#define NROWS (BATCH*SEQL)          // 4096
#define QKVLD 2304                  // concat QKV row stride
#define KCAT  6144                  // concat FFN hidden width

// ---------------- scratch (static device globals; no allocation) ----------------
__device__ float g_mask [DIM];
__device__ float g_xn   [NROWS*DIM];
__device__ float g_qkv  [(size_t)NROWS*QKVLD];
__device__ float g_attn [NROWS*DIM];
__device__ float g_x1   [NROWS*DIM];
__device__ float g_xm   [NROWS*DIM];
__device__ float g_xs   [NROWS*DIM];
__device__ float g_hcat [(size_t)NROWS*KCAT];
__device__ float g_wqkv [QKVLD*DIM];
__device__ float g_w1cat[(size_t)KCAT*DIM];
__device__ float g_w2cat[(size_t)DIM*KCAT];
__device__ float g_woc  [DIM*DIM];

// ---------------- helpers ----------------
__device__ __forceinline__ float gelu_f(float x) {
    return 0.5f * x * (1.f + erff(x * 0.70710678118654752f));
}
__device__ __forceinline__ float silu_f(float x) {
    return x / (1.f + expf(-x));
}
__device__ __forceinline__ unsigned f2tf(float f) {
    unsigned u; asm("cvt.rna.tf32.f32 %0, %1;" : "=r"(u) : "f"(f)); return u;
}
__device__ __forceinline__ float tf(float f) { return __uint_as_float(f2tf(f)); }

// m16n8k8 tf32 mma: D += A(16x8 row) * B(8x8 col)
__device__ __forceinline__ void mma8(float* c, const unsigned* a, const unsigned* b) {
    asm volatile(
        "mma.sync.aligned.m16n8k8.row.col.f32.tf32.tf32.f32 "
        "{%0,%1,%2,%3}, {%4,%5,%6,%7}, {%8,%9}, {%0,%1,%2,%3};\n"
        : "+f"(c[0]), "+f"(c[1]), "+f"(c[2]), "+f"(c[3])
        : "r"(a[0]), "r"(a[1]), "r"(a[2]), "r"(a[3]), "r"(b[0]), "r"(b[1]));
}

__device__ __forceinline__ void cp16(unsigned dst, const float* src) {
    asm volatile("cp.async.cg.shared.global [%0], [%1], 16;\n" :: "r"(dst), "l"(src));
}
__device__ __forceinline__ void cp_commit() { asm volatile("cp.async.commit_group;\n"); }
template<int N> __device__ __forceinline__ void cp_wait() {
    asm volatile("cp.async.wait_group %0;\n" :: "n"(N));
}

// ---------------- timelike_mask decode (dtype-robust: f32 / i32 / bool8) ----------------
__global__ void decode_mask_kernel(const void* __restrict__ raw) {
    __shared__ int cls;
    if (threadIdx.x == 0) {
        const unsigned* w = (const unsigned*)raw;
        int isFloat = 0, isByte = 0;
        for (int i = 0; i < 192; i++) {
            unsigned v = w[i];
            if (v == 0x3F800000u) isFloat = 1;
            if (v != 0u) {
                bool bytes01 = true, hi = false;
                for (int b = 0; b < 4; b++) {
                    unsigned by = (v >> (8*b)) & 0xffu;
                    if (by > 1u) bytes01 = false;
                    if (b > 0 && by) hi = true;
                }
                if (bytes01 && hi) isByte = 1;
            }
        }
        cls = isFloat ? 0 : (isByte ? 2 : 1);
    }
    __syncthreads();
    int c = cls;
    for (int i = threadIdx.x; i < DIM; i += blockDim.x) {
        float mv;
        if (c == 0)      mv = ((const float*)raw)[i];
        else if (c == 1) mv = (float)(((const int*)raw)[i] != 0);
        else             mv = (float)(((const unsigned char*)raw)[i] != 0);
        g_mask[i] = mv;
    }
}

// ---------------- weight prep: concat + tf32-round (replaces memcpys) ----------------
__global__ __launch_bounds__(256) void prep_wqkv(
    const float* __restrict__ Wq, const float* __restrict__ Wk,
    const float* __restrict__ Wv, float* __restrict__ o)
{
    int i = blockIdx.x * 256 + threadIdx.x;              // word index
    int r = i / DIM, c = i % DIM;
    float v = (r < DIM) ? Wq[r*DIM + c]
            : (r < 2*DIM) ? Wk[(r-DIM)*DIM + c] : Wv[(r-2*DIM)*DIM + c];
    o[i] = tf(v);
}
__global__ __launch_bounds__(256) void prep_w1cat(
    const float* __restrict__ w1, const float* __restrict__ w1t,
    const float* __restrict__ w1s, float* __restrict__ o)
{
    int i = blockIdx.x * 256 + threadIdx.x;
    int r = i / DIM, c = i % DIM;
    float v = (r < DFF) ? w1[r*DIM + c]
            : (r < DFF+DFFH) ? w1t[(r-DFF)*DIM + c] : w1s[(r-DFF-DFFH)*DIM + c];
    o[i] = tf(v);
}
__global__ __launch_bounds__(256) void prep_w2cat(
    const float* __restrict__ w2, const float* __restrict__ w2t,
    const float* __restrict__ w2s, float* __restrict__ o)
{
    int i = blockIdx.x * 256 + threadIdx.x;
    int r = i / KCAT, c = i % KCAT;
    float v = (c < DFF) ? w2[r*DFF + c]
            : (c < DFF+DFFH) ? w2t[r*DFFH + c - DFF] : w2s[r*DFFH + c - DFF - DFFH];
    o[i] = tf(v);
}
__global__ __launch_bounds__(256) void prep_woc(
    const float* __restrict__ Wo, float* __restrict__ o)
{
    int i = blockIdx.x * 256 + threadIdx.x;
    o[i] = tf(Wo[i]);
}

// ---------------- Minkowski LayerNorm (tf32-rounded output; optional mask split) ----------------
template<int SPLIT>
__global__ __launch_bounds__(256) void mink_norm_kernel(
    const float* __restrict__ x, const float* __restrict__ w,
    const float* __restrict__ bb, float* __restrict__ out,
    float* __restrict__ om, float* __restrict__ os)
{
    __shared__ float sA[8], sB[8];
    int row = blockIdx.x, t = threadIdx.x;
    const float* xr = x + (size_t)row * DIM;
    float v0 = xr[t], v1 = xr[t+256], v2 = xr[t+512];
    int lane = t & 31, wp = t >> 5;

    float s = v0 + v1 + v2;
    #pragma unroll
    for (int o = 16; o; o >>= 1) s += __shfl_xor_sync(0xffffffffu, s, o);
    if (!lane) sA[wp] = s;
    __syncthreads();
    float tot = 0.f;
    #pragma unroll
    for (int i = 0; i < 8; i++) tot += sA[i];
    float mean = tot * (1.f / DIM);

    float c0 = v0 - mean, c1 = v1 - mean, c2 = v2 - mean;
    float m0 = g_mask[t], m1 = g_mask[t+256], m2 = g_mask[t+512];
    float s2  = c0*c0 + c1*c1 + c2*c2;
    float s2m = c0*c0*m0 + c1*c1*m1 + c2*c2*m2;
    #pragma unroll
    for (int o = 16; o; o >>= 1) {
        s2  += __shfl_xor_sync(0xffffffffu, s2,  o);
        s2m += __shfl_xor_sync(0xffffffffu, s2m, o);
    }
    __syncthreads();
    if (!lane) { sA[wp] = s2; sB[wp] = s2m; }
    __syncthreads();
    float S2 = 0.f, S2m = 0.f;
    #pragma unroll
    for (int i = 0; i < 8; i++) { S2 += sA[i]; S2m += sB[i]; }

    float var = S2 * (1.f / DIM);
    float eta = S2 - 2.f * S2m;
    float kk  = 0.5f * (rsqrtf(var + 1e-5f) + rsqrtf(fabsf(eta) + 1e-5f));

    float y0 = tf(w[t]     * (c0 * kk) + bb[t]);
    float y1 = tf(w[t+256] * (c1 * kk) + bb[t+256]);
    float y2 = tf(w[t+512] * (c2 * kk) + bb[t+512]);
    size_t o0 = (size_t)row * DIM + t;
    out[o0] = y0; out[o0+256] = y1; out[o0+512] = y2;
    if (SPLIT) {
        om[o0]     = y0 * m0;        om[o0+256] = y1 * m1;        om[o0+512] = y2 * m2;
        os[o0]     = y0 * (1.f-m0);  os[o0+256] = y1 * (1.f-m1);  os[o0+512] = y2 * (1.f-m2);
    }
}

// ---------------- tf32 tensor-core NT GEMM core (multistage cp.async) ----------------
// Operands MUST already be tf32-rounded (HW truncation becomes identity).
#define BM 128
#define BN 128
#define BKT 16
#define ASTR 20
#define A_WORDS (BM*ASTR)               // 2560
#define STAGE_WORDS (2*A_WORDS)         // A tile then B tile
#define STAGE_BYTES (STAGE_WORDS*4)     // 20480
#define STAGES 4
#define GEMM_SMEM (STAGES*STAGE_BYTES)  // 81920

__device__ __forceinline__ void gemm_core(
    const float* __restrict__ A, const float* __restrict__ B,
    int K, int bm, int bn, float (&acc)[4][4][4])
{
    extern __shared__ float sh[];
    unsigned shBase = (unsigned)__cvta_generic_to_shared(sh);
    int tid = threadIdx.x;
    int lane = tid & 31, wid = tid >> 5;
    int wm = wid & 1, wn = wid >> 1;          // 2 x 4 warp grid
    int g = lane >> 2, t = lane & 3;
    int lr = tid >> 2;                        // 0..63
    int lk = (tid & 3) << 2;                  // 0,4,8,12

    const float* Ap = A + (size_t)(bm + lr) * K + lk;
    const float* Bp = B + (size_t)(bn + lr) * K + lk;

    int nk = K / BKT;
    #pragma unroll
    for (int s = 0; s < STAGES-1; s++) {
        unsigned st = shBase + s * STAGE_BYTES;
        cp16(st + (lr*ASTR + lk)*4,                Ap + s*BKT);
        cp16(st + ((lr+64)*ASTR + lk)*4,           Ap + (size_t)64*K + s*BKT);
        cp16(st + (A_WORDS + lr*ASTR + lk)*4,      Bp + s*BKT);
        cp16(st + (A_WORDS + (lr+64)*ASTR + lk)*4, Bp + (size_t)64*K + s*BKT);
        cp_commit();
    }

    for (int kt = 0; kt < nk; kt++) {
        cp_wait<STAGES-2>();
        __syncthreads();

        int pf = kt + STAGES - 1;
        if (pf < nk) {
            unsigned st = shBase + (pf % STAGES) * STAGE_BYTES;
            cp16(st + (lr*ASTR + lk)*4,                Ap + pf*BKT);
            cp16(st + ((lr+64)*ASTR + lk)*4,           Ap + (size_t)64*K + pf*BKT);
            cp16(st + (A_WORDS + lr*ASTR + lk)*4,      Bp + pf*BKT);
            cp16(st + (A_WORDS + (lr+64)*ASTR + lk)*4, Bp + (size_t)64*K + pf*BKT);
        }
        cp_commit();

        const float* Ab = sh + (kt % STAGES) * STAGE_WORDS;
        const float* Bb = Ab + A_WORDS;
        #pragma unroll
        for (int k8 = 0; k8 < BKT; k8 += 8) {
            unsigned af[4][4], bf[4][2];
            #pragma unroll
            for (int mt = 0; mt < 4; mt++) {
                const float* p = &Ab[(wm*64 + mt*16 + g)*ASTR + k8 + t];
                af[mt][0] = __float_as_uint(p[0]);
                af[mt][1] = __float_as_uint(p[8*ASTR]);
                af[mt][2] = __float_as_uint(p[4]);
                af[mt][3] = __float_as_uint(p[8*ASTR + 4]);
            }
            #pragma unroll
            for (int nt = 0; nt < 4; nt++) {
                const float* p = &Bb[(wn*32 + nt*8 + g)*ASTR + k8 + t];
                bf[nt][0] = __float_as_uint(p[0]);
                bf[nt][1] = __float_as_uint(p[4]);
            }
            #pragma unroll
            for (int mt = 0; mt < 4; mt++)
                #pragma unroll
                for (int nt = 0; nt < 4; nt++)
                    mma8(acc[mt][nt], af[mt], bf[nt]);
        }
    }
}

// epilogue: act (runtime, uniform), alpha, optional residual, optional tf32-round
__device__ __forceinline__ void store_epi(
    float (&acc)[4][4][4], float* __restrict__ C, const float* __restrict__ resid,
    int ldc, float alpha, int bm, int bn, int act, int tfout)
{
    int tid = threadIdx.x, lane = tid & 31, wid = tid >> 5;
    int wm = wid & 1, wn = wid >> 1;
    int g = lane >> 2, t = lane & 3;
    #pragma unroll
    for (int mt = 0; mt < 4; mt++) {
        int r0 = bm + wm*64 + mt*16 + g;
        #pragma unroll
        for (int nt = 0; nt < 4; nt++) {
            int c = bn + wn*32 + nt*8 + (t << 1);
            #pragma unroll
            for (int hh = 0; hh < 2; hh++) {
                float v0 = acc[mt][nt][2*hh];
                float v1 = acc[mt][nt][2*hh + 1];
                if (act == 1) { v0 = gelu_f(v0); v1 = gelu_f(v1); }
                else if (act == 2) { v0 = silu_f(v0); v1 = silu_f(v1); }
                v0 *= alpha; v1 *= alpha;
                size_t idx = (size_t)(r0 + 8*hh) * ldc + c;
                if (resid) {
                    float2 rv = *(const float2*)(resid + idx);
                    v0 += rv.x; v1 += rv.y;
                }
                if (tfout) { v0 = tf(v0); v1 = tf(v1); }
                *(float2*)(C + idx) = make_float2(v0, v1);
            }
        }
    }
}

template<int TFOUT>
__global__ __launch_bounds__(256, 2) void tgemm(
    const float* __restrict__ A, const float* __restrict__ B,
    float* __restrict__ C, const float* __restrict__ resid,
    int K, int ldc, float alpha)
{
    float acc[4][4][4] = {};
    int bm = blockIdx.y * BM, bn = blockIdx.x * BN;
    gemm_core(A, B, K, bm, bn, acc);
    store_epi(acc, C, resid, ldc, alpha, bm, bn, 0, TFOUT);
}

// fused FFN up-projection: per-block-column A-pointer + activation select
__global__ __launch_bounds__(256, 2) void ffn_up(
    const float* __restrict__ xn, const float* __restrict__ xm,
    const float* __restrict__ xs, const float* __restrict__ w1cat,
    float* __restrict__ hcat)
{
    int bn = blockIdx.x * BN, bm = blockIdx.y * BM;
    const float* A; int act;
    if (bn < DFF)             { A = xn; act = 1; }
    else if (bn < DFF + DFFH) { A = xm; act = 2; }
    else                      { A = xs; act = 1; }
    float acc[4][4][4] = {};
    gemm_core(A, w1cat, DIM, bm, bn, acc);
    store_epi(acc, hcat, nullptr, KCAT, 1.f, bm, bn, act, 1);
}

// ---------------- fold Lorentz sf + 1/sqrt(DH) into Q ----------------
__global__ __launch_bounds__(256) void qeff_kernel(float* __restrict__ qkv)
{
    int gw   = (blockIdx.x * blockDim.x + threadIdx.x) >> 5;
    int lane = threadIdx.x & 31;
    if (gw >= NROWS * NHEAD) return;
    int row = gw / NHEAD, h = gw % NHEAD;
    float* qp = qkv + (size_t)row * QKVLD + h * DHEAD;
    float a = qp[lane], c = qp[lane + 32];
    float ma = g_mask[h * DHEAD + lane], mc = g_mask[h * DHEAD + lane + 32];
    float qn2  = a*a + c*c;
    float qtn2 = a*a*ma + c*c*mc;
    #pragma unroll
    for (int o = 16; o; o >>= 1) {
        qn2  += __shfl_xor_sync(0xffffffffu, qn2,  o);
        qtn2 += __shfl_xor_sync(0xffffffffu, qtn2, o);
    }
    float qtn = sqrtf(qtn2);
    float sf  = (qtn > 1e-6f) ? sqrtf(qn2) / fmaxf(qtn, 1e-8f) : 0.f;
    qp[lane]      = tf(a * (1.f - 0.5f * sf * ma) * 0.125f);   // fold 1/sqrt(64)
    qp[lane + 32] = tf(c * (1.f - 0.5f * sf * mc) * 0.125f);
}

// ---------------- tf32 tensor-core causal flash attention ----------------
// BQ=128, BK=64, 256 threads (8 warps). Inputs pre-rounded to tf32.
#define FS 68
#define FA_SMEM (384 * FS * 4)

__global__ __launch_bounds__(256) void flash_tc(
    const float* __restrict__ QKV, float* __restrict__ O)
{
    extern __shared__ float sm[];
    float* Qs = sm;                   // [128][FS]  rows i, cols d
    float* Ks = sm + 128 * FS;        // [64][FS]   rows j, cols d
    float* Vt = sm + 192 * FS;        // [64][FS]   rows d, cols j (transposed)
    float* Ps = sm + 256 * FS;        // [128][FS]  warp-private P slices

    int tid = threadIdx.x, lane = tid & 31, wid = tid >> 5;
    int g = lane >> 2, t = lane & 3;
    int bid = blockIdx.x;
    int qb = 15 - bid / 24;           // long blocks first
    int bh = bid % 24;
    int b = bh / NHEAD, h = bh % NHEAD;

    const float* Qp = QKV + (size_t)(b * SEQL + qb * 128) * QKVLD + h * DHEAD;
    const float* Kp = QKV + (size_t)(b * SEQL) * QKVLD + DIM + h * DHEAD;
    const float* Vp = Kp + DIM;

    #pragma unroll
    for (int it = 0; it < 8; it++) {
        int idx = tid + it * 256;
        int r = idx >> 4, c4 = (idx & 15) << 2;
        *(float4*)&Qs[r * FS + c4] = *(const float4*)(Qp + (size_t)r * QKVLD + c4);
    }

    float oacc[8][4] = {};
    float mrun[2] = {-1e30f, -1e30f}, lrun[2] = {0.f, 0.f};
    int rbase = qb * 128 + wid * 16;
    int kmax = 2 * qb + 2;

    for (int kt = 0; kt < kmax; kt++) {
        __syncthreads();
        #pragma unroll
        for (int it = 0; it < 4; it++) {
            int idx = tid + it * 256;
            int r = idx >> 4, c4 = (idx & 15) << 2;
            *(float4*)&Ks[r * FS + c4] =
                *(const float4*)(Kp + (size_t)(kt * 64 + r) * QKVLD + c4);
            float4 w = *(const float4*)(Vp + (size_t)(kt * 64 + r) * QKVLD + c4);
            Vt[(c4 + 0) * FS + r] = w.x;
            Vt[(c4 + 1) * FS + r] = w.y;
            Vt[(c4 + 2) * FS + r] = w.z;
            Vt[(c4 + 3) * FS + r] = w.w;
        }
        __syncthreads();

        // S = Q @ K^T  (scale pre-folded into Q)
        float s[8][4] = {};
        #pragma unroll
        for (int k8 = 0; k8 < 64; k8 += 8) {
            unsigned aq[4];
            const float* qp2 = &Qs[(wid * 16 + g) * FS + k8 + t];
            aq[0] = __float_as_uint(qp2[0]);
            aq[1] = __float_as_uint(qp2[8 * FS]);
            aq[2] = __float_as_uint(qp2[4]);
            aq[3] = __float_as_uint(qp2[8 * FS + 4]);
            #pragma unroll
            for (int nt = 0; nt < 8; nt++) {
                unsigned bk[2];
                const float* kp2 = &Ks[(nt * 8 + g) * FS + k8 + t];
                bk[0] = __float_as_uint(kp2[0]);
                bk[1] = __float_as_uint(kp2[4]);
                mma8(s[nt], aq, bk);
            }
        }

        if (kt * 64 + 63 > rbase) {
            int r0 = rbase + g, r1 = r0 + 8;
            #pragma unroll
            for (int nt = 0; nt < 8; nt++) {
                int c0 = kt * 64 + nt * 8 + t * 2;
                if (c0     > r0) s[nt][0] = -1e30f;
                if (c0 + 1 > r0) s[nt][1] = -1e30f;
                if (c0     > r1) s[nt][2] = -1e30f;
                if (c0 + 1 > r1) s[nt][3] = -1e30f;
            }
        }

        #pragma unroll
        for (int r = 0; r < 2; r++) {
            float rm = -1e30f;
            #pragma unroll
            for (int nt = 0; nt < 8; nt++)
                rm = fmaxf(rm, fmaxf(s[nt][2*r], s[nt][2*r + 1]));
            rm = fmaxf(rm, __shfl_xor_sync(0xffffffffu, rm, 1));
            rm = fmaxf(rm, __shfl_xor_sync(0xffffffffu, rm, 2));
            float mn = fmaxf(mrun[r], rm);
            float sc = __expf(mrun[r] - mn);
            float rs = 0.f;
            #pragma unroll
            for (int nt = 0; nt < 8; nt++) {
                s[nt][2*r]     = __expf(s[nt][2*r]     - mn);
                s[nt][2*r + 1] = __expf(s[nt][2*r + 1] - mn);
                rs += s[nt][2*r] + s[nt][2*r + 1];
            }
            rs += __shfl_xor_sync(0xffffffffu, rs, 1);
            rs += __shfl_xor_sync(0xffffffffu, rs, 2);
            lrun[r] = lrun[r] * sc + rs;
            mrun[r] = mn;
            #pragma unroll
            for (int nt = 0; nt < 8; nt++) {
                oacc[nt][2*r]     *= sc;
                oacc[nt][2*r + 1] *= sc;
            }
        }

        #pragma unroll
        for (int nt = 0; nt < 8; nt++) {
            int c = nt * 8 + t * 2;
            Ps[(wid * 16 + g    ) * FS + c    ] = tf(s[nt][0]);
            Ps[(wid * 16 + g    ) * FS + c + 1] = tf(s[nt][1]);
            Ps[(wid * 16 + g + 8) * FS + c    ] = tf(s[nt][2]);
            Ps[(wid * 16 + g + 8) * FS + c + 1] = tf(s[nt][3]);
        }
        __syncwarp();

        #pragma unroll
        for (int k8 = 0; k8 < 64; k8 += 8) {
            unsigned ap[4];
            const float* pp = &Ps[(wid * 16 + g) * FS + k8 + t];
            ap[0] = __float_as_uint(pp[0]);
            ap[1] = __float_as_uint(pp[8 * FS]);
            ap[2] = __float_as_uint(pp[4]);
            ap[3] = __float_as_uint(pp[8 * FS + 4]);
            #pragma unroll
            for (int nt = 0; nt < 8; nt++) {
                unsigned bv[2];
                const float* vp2 = &Vt[(nt * 8 + g) * FS + k8 + t];
                bv[0] = __float_as_uint(vp2[0]);
                bv[1] = __float_as_uint(vp2[4]);
                mma8(oacc[nt], ap, bv);
            }
        }
    }

    float i0 = 1.f / lrun[0], i1 = 1.f / lrun[1];
    size_t grow0 = (size_t)b * SEQL + qb * 128 + wid * 16 + g;
    #pragma unroll
    for (int nt = 0; nt < 8; nt++) {
        int c = h * DHEAD + nt * 8 + t * 2;
        *(float2*)&O[grow0 * DIM + c] =
            make_float2(tf(oacc[nt][0] * i0), tf(oacc[nt][1] * i0));
        *(float2*)&O[(grow0 + 8) * DIM + c] =
            make_float2(tf(oacc[nt][2] * i1), tf(oacc[nt][3] * i1));
    }
}

// ---------------- host launcher ----------------
extern "C" void kernel_launch(void* const* d_in, const int* in_sizes, int n_in,
                              void* d_out, int out_size)
{
    const float* x    = (const float*)d_in[0];
    const void*  tmsk = d_in[2];
    const float* Wq   = (const float*)d_in[3];
    const float* Wk   = (const float*)d_in[4];
    const float* Wv   = (const float*)d_in[5];
    const float* Wo   = (const float*)d_in[6];
    const float* w1   = (const float*)d_in[7];
    const float* w2   = (const float*)d_in[8];
    const float* w1t  = (const float*)d_in[9];
    const float* w2t  = (const float*)d_in[10];
    const float* w1s  = (const float*)d_in[11];
    const float* w2s  = (const float*)d_in[12];
    const float* n1w  = (const float*)d_in[13];
    const float* n1b  = (const float*)d_in[14];
    const float* n2w  = (const float*)d_in[15];
    const float* n2b  = (const float*)d_in[16];
    float* out = (float*)d_out;

    float *p_xn, *p_qkv, *p_attn, *p_x1, *p_xm, *p_xs, *p_hcat;
    float *p_wqkv, *p_w1cat, *p_w2cat, *p_woc;
    cudaGetSymbolAddress((void**)&p_xn,    g_xn);
    cudaGetSymbolAddress((void**)&p_qkv,   g_qkv);
    cudaGetSymbolAddress((void**)&p_attn,  g_attn);
    cudaGetSymbolAddress((void**)&p_x1,    g_x1);
    cudaGetSymbolAddress((void**)&p_xm,    g_xm);
    cudaGetSymbolAddress((void**)&p_xs,    g_xs);
    cudaGetSymbolAddress((void**)&p_hcat,  g_hcat);
    cudaGetSymbolAddress((void**)&p_wqkv,  g_wqkv);
    cudaGetSymbolAddress((void**)&p_w1cat, g_w1cat);
    cudaGetSymbolAddress((void**)&p_w2cat, g_w2cat);
    cudaGetSymbolAddress((void**)&p_woc,   g_woc);

    static int attr_done = 0;
    if (!attr_done) {
        cudaFuncSetAttribute(tgemm<0>, cudaFuncAttributeMaxDynamicSharedMemorySize, GEMM_SMEM);
        cudaFuncSetAttribute(tgemm<1>, cudaFuncAttributeMaxDynamicSharedMemorySize, GEMM_SMEM);
        cudaFuncSetAttribute(ffn_up,   cudaFuncAttributeMaxDynamicSharedMemorySize, GEMM_SMEM);
        cudaFuncSetAttribute(flash_tc, cudaFuncAttributeMaxDynamicSharedMemorySize, FA_SMEM);
        attr_done = 1;
    }

    decode_mask_kernel<<<1, 256>>>(tmsk);

    // weight prep (concat + tf32 rounding)
    prep_wqkv <<<QKVLD*DIM/256, 256>>>(Wq, Wk, Wv, p_wqkv);
    prep_w1cat<<<(size_t)KCAT*DIM/256, 256>>>(w1, w1t, w1s, p_w1cat);
    prep_w2cat<<<(size_t)DIM*KCAT/256, 256>>>(w2, w2t, w2s, p_w2cat);
    prep_woc  <<<DIM*DIM/256, 256>>>(Wo, p_woc);

    // ---- attention path ----
    mink_norm_kernel<0><<<NROWS, 256>>>(x, n1w, n1b, p_xn, nullptr, nullptr);

    tgemm<1><<<dim3(QKVLD/BN, NROWS/BM), 256, GEMM_SMEM>>>(
        p_xn, p_wqkv, p_qkv, nullptr, DIM, QKVLD, 1.f);
    qeff_kernel<<<(NROWS * NHEAD * 32) / 256, 256>>>(p_qkv);

    flash_tc<<<16 * 24, 256, FA_SMEM>>>(p_qkv, p_attn);

    // x1 = x + attn @ Wo^T
    tgemm<0><<<dim3(DIM/BN, NROWS/BM), 256, GEMM_SMEM>>>(
        p_attn, p_woc, p_x1, x, DIM, DIM, 1.f);

    // ---- FFN path ----
    mink_norm_kernel<1><<<NROWS, 256>>>(p_x1, n2w, n2b, p_xn, p_xm, p_xs);

    ffn_up<<<dim3(KCAT/BN, NROWS/BM), 256, GEMM_SMEM>>>(
        p_xn, p_xm, p_xs, p_w1cat, p_hcat);

    // out = x1 + 0.5 * hcat @ w2cat^T   (single K=6144 GEMM)
    tgemm<0><<<dim3(DIM/BN, NROWS/BM), 256, GEMM_SMEM>>>(
        p_hcat, p_w2cat, out, p_x1, KCAT, DIM, 0.5f);
}

// round 7
// speedup vs baseline: 6.0337x; 2.0265x over previous
#include <cuda_runtime.h>
#include <cuda_bf16.h>
#include <math.h>

typedef __nv_bfloat16 bf16;

// Problem constants
#define BATCH 2
#define SEQL  2048
#define DIM   768
#define NHEAD 12
#define DHEAD 64
#define DFF   3072
#define DFFH  1536
#define NROWS (BATCH*SEQL)          // 4096
#define QKVLD 2304                  // concat QKV row stride
#define KCAT  6144                  // concat FFN hidden width

// ---------------- scratch (static device globals; no allocation) ----------------
__device__ float g_mask [DIM];
__device__ bf16  g_xn   [NROWS*DIM];
__device__ bf16  g_qkv  [(size_t)NROWS*QKVLD];
__device__ bf16  g_attn [NROWS*DIM];
__device__ float g_x1   [NROWS*DIM];
__device__ bf16  g_xm   [NROWS*DIM];
__device__ bf16  g_xs   [NROWS*DIM];
__device__ bf16  g_hcat [(size_t)NROWS*KCAT];
__device__ bf16  g_wqkv [QKVLD*DIM];
__device__ bf16  g_w1cat[(size_t)KCAT*DIM];
__device__ bf16  g_w2cat[(size_t)DIM*KCAT];
__device__ bf16  g_woc  [DIM*DIM];

// ---------------- helpers ----------------
__device__ __forceinline__ float gelu_f(float x) {
    return 0.5f * x * (1.f + erff(x * 0.70710678118654752f));
}
__device__ __forceinline__ float silu_f(float x) {
    return x / (1.f + expf(-x));
}
__device__ __forceinline__ __nv_bfloat162 pack_bf2(float a, float b) {
    return __float22bfloat162_rn(make_float2(a, b));
}

// m16n8k16 bf16 mma: D += A(16x16 row) * B(16x8 col-of-NT)
__device__ __forceinline__ void mma16(float* c, const unsigned* a,
                                      unsigned b0, unsigned b1) {
    asm volatile(
        "mma.sync.aligned.m16n8k16.row.col.f32.bf16.bf16.f32 "
        "{%0,%1,%2,%3}, {%4,%5,%6,%7}, {%8,%9}, {%0,%1,%2,%3};\n"
        : "+f"(c[0]), "+f"(c[1]), "+f"(c[2]), "+f"(c[3])
        : "r"(a[0]), "r"(a[1]), "r"(a[2]), "r"(a[3]), "r"(b0), "r"(b1));
}
__device__ __forceinline__ void ldsm4(unsigned* r, unsigned addr) {
    asm volatile("ldmatrix.sync.aligned.m8n8.x4.shared.b16 {%0,%1,%2,%3}, [%4];"
        : "=r"(r[0]), "=r"(r[1]), "=r"(r[2]), "=r"(r[3]) : "r"(addr));
}
__device__ __forceinline__ void cp16(unsigned dst, const void* src) {
    asm volatile("cp.async.cg.shared.global [%0], [%1], 16;\n" :: "r"(dst), "l"(src));
}
__device__ __forceinline__ void cp_commit() { asm volatile("cp.async.commit_group;\n"); }
template<int N> __device__ __forceinline__ void cp_wait() {
    asm volatile("cp.async.wait_group %0;\n" :: "n"(N));
}

// ---------------- timelike_mask decode (dtype-robust: f32 / i32 / bool8) ----------------
__global__ void decode_mask_kernel(const void* __restrict__ raw) {
    __shared__ int cls;
    if (threadIdx.x == 0) {
        const unsigned* w = (const unsigned*)raw;
        int isFloat = 0, isByte = 0;
        for (int i = 0; i < 192; i++) {
            unsigned v = w[i];
            if (v == 0x3F800000u) isFloat = 1;
            if (v != 0u) {
                bool bytes01 = true, hi = false;
                for (int b = 0; b < 4; b++) {
                    unsigned by = (v >> (8*b)) & 0xffu;
                    if (by > 1u) bytes01 = false;
                    if (b > 0 && by) hi = true;
                }
                if (bytes01 && hi) isByte = 1;
            }
        }
        cls = isFloat ? 0 : (isByte ? 2 : 1);
    }
    __syncthreads();
    int c = cls;
    for (int i = threadIdx.x; i < DIM; i += blockDim.x) {
        float mv;
        if (c == 0)      mv = ((const float*)raw)[i];
        else if (c == 1) mv = (float)(((const int*)raw)[i] != 0);
        else             mv = (float)(((const unsigned char*)raw)[i] != 0);
        g_mask[i] = mv;
    }
}

// ---------------- weight prep: concat + bf16 convert (vectorized) ----------------
__global__ __launch_bounds__(256) void prep_wqkv(
    const float* __restrict__ Wq, const float* __restrict__ Wk,
    const float* __restrict__ Wv, bf16* __restrict__ o)
{
    int i4 = blockIdx.x * 256 + threadIdx.x;
    int i = i4 * 4;
    int r = i / DIM, c = i % DIM;
    const float* src = (r < DIM) ? (Wq + r*DIM + c)
                     : (r < 2*DIM) ? (Wk + (r-DIM)*DIM + c) : (Wv + (r-2*DIM)*DIM + c);
    float4 v = *(const float4*)src;
    *(__nv_bfloat162*)&o[i]     = pack_bf2(v.x, v.y);
    *(__nv_bfloat162*)&o[i + 2] = pack_bf2(v.z, v.w);
}
__global__ __launch_bounds__(256) void prep_w1cat(
    const float* __restrict__ w1, const float* __restrict__ w1t,
    const float* __restrict__ w1s, bf16* __restrict__ o)
{
    int i4 = blockIdx.x * 256 + threadIdx.x;
    int i = i4 * 4;
    int r = i / DIM, c = i % DIM;
    const float* src = (r < DFF) ? (w1 + r*DIM + c)
                     : (r < DFF+DFFH) ? (w1t + (r-DFF)*DIM + c)
                     : (w1s + (size_t)(r-DFF-DFFH)*DIM + c);
    float4 v = *(const float4*)src;
    *(__nv_bfloat162*)&o[i]     = pack_bf2(v.x, v.y);
    *(__nv_bfloat162*)&o[i + 2] = pack_bf2(v.z, v.w);
}
__global__ __launch_bounds__(256) void prep_w2cat(
    const float* __restrict__ w2, const float* __restrict__ w2t,
    const float* __restrict__ w2s, bf16* __restrict__ o)
{
    int i4 = blockIdx.x * 256 + threadIdx.x;
    size_t i = (size_t)i4 * 4;
    int r = (int)(i / KCAT), c = (int)(i % KCAT);
    const float* src = (c < DFF) ? (w2 + (size_t)r*DFF + c)
                     : (c < DFF+DFFH) ? (w2t + (size_t)r*DFFH + c - DFF)
                     : (w2s + (size_t)r*DFFH + c - DFF - DFFH);
    float4 v = *(const float4*)src;
    *(__nv_bfloat162*)&o[i]     = pack_bf2(v.x, v.y);
    *(__nv_bfloat162*)&o[i + 2] = pack_bf2(v.z, v.w);
}
__global__ __launch_bounds__(256) void prep_woc(
    const float* __restrict__ Wo, bf16* __restrict__ o)
{
    int i = (blockIdx.x * 256 + threadIdx.x) * 4;
    float4 v = *(const float4*)(Wo + i);
    *(__nv_bfloat162*)&o[i]     = pack_bf2(v.x, v.y);
    *(__nv_bfloat162*)&o[i + 2] = pack_bf2(v.z, v.w);
}

// ---------------- Minkowski LayerNorm (bf16 output; optional mask split) ----------------
template<int SPLIT>
__global__ __launch_bounds__(256) void mink_norm_kernel(
    const float* __restrict__ x, const float* __restrict__ w,
    const float* __restrict__ bb, bf16* __restrict__ out,
    bf16* __restrict__ om, bf16* __restrict__ os)
{
    __shared__ float sA[8], sB[8];
    int row = blockIdx.x, t = threadIdx.x;
    const float* xr = x + (size_t)row * DIM;
    float v0 = xr[t], v1 = xr[t+256], v2 = xr[t+512];
    int lane = t & 31, wp = t >> 5;

    float s = v0 + v1 + v2;
    #pragma unroll
    for (int o = 16; o; o >>= 1) s += __shfl_xor_sync(0xffffffffu, s, o);
    if (!lane) sA[wp] = s;
    __syncthreads();
    float tot = 0.f;
    #pragma unroll
    for (int i = 0; i < 8; i++) tot += sA[i];
    float mean = tot * (1.f / DIM);

    float c0 = v0 - mean, c1 = v1 - mean, c2 = v2 - mean;
    float m0 = g_mask[t], m1 = g_mask[t+256], m2 = g_mask[t+512];
    float s2  = c0*c0 + c1*c1 + c2*c2;
    float s2m = c0*c0*m0 + c1*c1*m1 + c2*c2*m2;
    #pragma unroll
    for (int o = 16; o; o >>= 1) {
        s2  += __shfl_xor_sync(0xffffffffu, s2,  o);
        s2m += __shfl_xor_sync(0xffffffffu, s2m, o);
    }
    __syncthreads();
    if (!lane) { sA[wp] = s2; sB[wp] = s2m; }
    __syncthreads();
    float S2 = 0.f, S2m = 0.f;
    #pragma unroll
    for (int i = 0; i < 8; i++) { S2 += sA[i]; S2m += sB[i]; }

    float var = S2 * (1.f / DIM);
    float eta = S2 - 2.f * S2m;
    float kk  = 0.5f * (rsqrtf(var + 1e-5f) + rsqrtf(fabsf(eta) + 1e-5f));

    float y0 = w[t]     * (c0 * kk) + bb[t];
    float y1 = w[t+256] * (c1 * kk) + bb[t+256];
    float y2 = w[t+512] * (c2 * kk) + bb[t+512];
    size_t o0 = (size_t)row * DIM + t;
    out[o0]     = __float2bfloat16_rn(y0);
    out[o0+256] = __float2bfloat16_rn(y1);
    out[o0+512] = __float2bfloat16_rn(y2);
    if (SPLIT) {
        om[o0]     = __float2bfloat16_rn(y0 * m0);
        om[o0+256] = __float2bfloat16_rn(y1 * m1);
        om[o0+512] = __float2bfloat16_rn(y2 * m2);
        os[o0]     = __float2bfloat16_rn(y0 * (1.f - m0));
        os[o0+256] = __float2bfloat16_rn(y1 * (1.f - m1));
        os[o0+512] = __float2bfloat16_rn(y2 * (1.f - m2));
    }
}

// ---------------- bf16 tensor-core NT GEMM core (multistage cp.async + ldmatrix) ----------------
// C[M,N] = A[M,K] @ B[N,K]^T.  MT = m-tiles per warp (BM = MT*32).
#define BKH 32                        // k elements per stage
#define LDH 40                        // smem row stride in halves (conflict-free)
#define STAGES 4

template<int MT>
__device__ __forceinline__ void gemm_core_bf(
    const bf16* __restrict__ A, const bf16* __restrict__ B,
    int K, int bm, int bn, float (&acc)[MT][4][4])
{
    constexpr int AROWS = MT * 32;
    constexpr int TILEA = AROWS * LDH;            // halves
    constexpr int TILEB = 128 * LDH;
    constexpr int STB   = (TILEA + TILEB) * 2;    // stage bytes
    extern __shared__ char shc[];
    unsigned shBase = (unsigned)__cvta_generic_to_shared(shc);

    int tid = threadIdx.x, lane = tid & 31, wid = tid >> 5;
    int wm = wid & 1, wn = wid >> 1;              // 2 x 4 warp grid
    int lr = tid >> 2;                            // 0..63
    int lc = (tid & 3) * 8;                       // halves chunk

    const bf16* Ap = A + (size_t)(bm + lr) * K + lc;
    const bf16* Bp = B + (size_t)(bn + lr) * K + lc;

    int nk = K / BKH;
    #pragma unroll
    for (int s = 0; s < STAGES-1; s++) {
        unsigned st = shBase + s * STB;
        const bf16* a = Ap + s * BKH;
        const bf16* b = Bp + s * BKH;
        cp16(st + (lr*LDH + lc)*2, a);
        if (MT == 4) cp16(st + ((lr+64)*LDH + lc)*2, a + (size_t)64*K);
        cp16(st + TILEA*2 + (lr*LDH + lc)*2, b);
        cp16(st + TILEA*2 + ((lr+64)*LDH + lc)*2, b + (size_t)64*K);
        cp_commit();
    }

    int lrow = lane & 15, lk8 = (lane >> 4) << 3;
    for (int kt = 0; kt < nk; kt++) {
        cp_wait<STAGES-2>();
        __syncthreads();

        int pf = kt + STAGES - 1;
        if (pf < nk) {
            unsigned st = shBase + (pf % STAGES) * STB;
            const bf16* a = Ap + pf * BKH;
            const bf16* b = Bp + pf * BKH;
            cp16(st + (lr*LDH + lc)*2, a);
            if (MT == 4) cp16(st + ((lr+64)*LDH + lc)*2, a + (size_t)64*K);
            cp16(st + TILEA*2 + (lr*LDH + lc)*2, b);
            cp16(st + TILEA*2 + ((lr+64)*LDH + lc)*2, b + (size_t)64*K);
        }
        cp_commit();

        unsigned sA = shBase + (kt % STAGES) * STB;
        unsigned sB = sA + TILEA * 2;
        #pragma unroll
        for (int ks = 0; ks < 2; ks++) {
            unsigned af[MT][4], bq[2][4];
            #pragma unroll
            for (int mt = 0; mt < MT; mt++)
                ldsm4(af[mt], sA + ((wm*(MT*16) + mt*16 + lrow)*LDH + ks*16 + lk8)*2);
            #pragma unroll
            for (int p = 0; p < 2; p++)
                ldsm4(bq[p], sB + ((wn*32 + p*16 + lrow)*LDH + ks*16 + lk8)*2);
            #pragma unroll
            for (int mt = 0; mt < MT; mt++)
                #pragma unroll
                for (int nt = 0; nt < 4; nt++)
                    mma16(acc[mt][nt], af[mt],
                          bq[nt>>1][nt&1], bq[nt>>1][(nt&1)+2]);
        }
    }
}

// epilogue: act (uniform), alpha, optional residual; OT: 0 fp32, 1 bf16
template<int MT, int OT>
__device__ __forceinline__ void store_epi(
    float (&acc)[MT][4][4], void* Cv, const float* __restrict__ resid,
    int ldc, float alpha, int bm, int bn, int act)
{
    int tid = threadIdx.x, lane = tid & 31, wid = tid >> 5;
    int wm = wid & 1, wn = wid >> 1;
    int g = lane >> 2, t = lane & 3;
    #pragma unroll
    for (int mt = 0; mt < MT; mt++) {
        int r0 = bm + wm*(MT*16) + mt*16 + g;
        #pragma unroll
        for (int nt = 0; nt < 4; nt++) {
            int c = bn + wn*32 + nt*8 + t*2;
            #pragma unroll
            for (int hh = 0; hh < 2; hh++) {
                float v0 = acc[mt][nt][2*hh];
                float v1 = acc[mt][nt][2*hh + 1];
                if (act == 1) { v0 = gelu_f(v0); v1 = gelu_f(v1); }
                else if (act == 2) { v0 = silu_f(v0); v1 = silu_f(v1); }
                v0 *= alpha; v1 *= alpha;
                size_t idx = (size_t)(r0 + 8*hh) * ldc + c;
                if (OT == 0) {
                    if (resid) {
                        float2 rv = *(const float2*)(resid + idx);
                        v0 += rv.x; v1 += rv.y;
                    }
                    *(float2*)((float*)Cv + idx) = make_float2(v0, v1);
                } else {
                    *(__nv_bfloat162*)((bf16*)Cv + idx) = pack_bf2(v0, v1);
                }
            }
        }
    }
}

template<int MT, int OT>
__global__ __launch_bounds__(256, 2) void tgemm(
    const bf16* __restrict__ A, const bf16* __restrict__ B,
    void* __restrict__ C, const float* __restrict__ resid,
    int K, int ldc, float alpha)
{
    float acc[MT][4][4] = {};
    int bm = blockIdx.y * (MT*32), bn = blockIdx.x * 128;
    gemm_core_bf<MT>(A, B, K, bm, bn, acc);
    store_epi<MT, OT>(acc, C, resid, ldc, alpha, bm, bn, 0);
}

// fused FFN up-projection: per-block-column A-pointer + activation select
__global__ __launch_bounds__(256, 2) void ffn_up(
    const bf16* __restrict__ xn, const bf16* __restrict__ xm,
    const bf16* __restrict__ xs, const bf16* __restrict__ w1cat,
    bf16* __restrict__ hcat)
{
    int bn = blockIdx.x * 128, bm = blockIdx.y * 128;
    const bf16* A; int act;
    if (bn < DFF)             { A = xn; act = 1; }
    else if (bn < DFF + DFFH) { A = xm; act = 2; }
    else                      { A = xs; act = 1; }
    float acc[4][4][4] = {};
    gemm_core_bf<4>(A, w1cat, DIM, bm, bn, acc);
    store_epi<4, 1>(acc, hcat, nullptr, KCAT, 1.f, bm, bn, act);
}

#define GEMM_SMEM_MT4 (STAGES * (4*32 + 128) * LDH * 2)   // 81920
#define GEMM_SMEM_MT2 (STAGES * (2*32 + 128) * LDH * 2)   // 61440

// ---------------- fold Lorentz sf + 1/sqrt(DH) into Q (bf16) ----------------
__global__ __launch_bounds__(256) void qeff_kernel(bf16* __restrict__ qkv)
{
    int gw   = (blockIdx.x * blockDim.x + threadIdx.x) >> 5;
    int lane = threadIdx.x & 31;
    if (gw >= NROWS * NHEAD) return;
    int row = gw / NHEAD, h = gw % NHEAD;
    bf16* qp = qkv + (size_t)row * QKVLD + h * DHEAD;
    float a = __bfloat162float(qp[lane]);
    float c = __bfloat162float(qp[lane + 32]);
    float ma = g_mask[h * DHEAD + lane], mc = g_mask[h * DHEAD + lane + 32];
    float qn2  = a*a + c*c;
    float qtn2 = a*a*ma + c*c*mc;
    #pragma unroll
    for (int o = 16; o; o >>= 1) {
        qn2  += __shfl_xor_sync(0xffffffffu, qn2,  o);
        qtn2 += __shfl_xor_sync(0xffffffffu, qtn2, o);
    }
    float qtn = sqrtf(qtn2);
    float sf  = (qtn > 1e-6f) ? sqrtf(qn2) / fmaxf(qtn, 1e-8f) : 0.f;
    qp[lane]      = __float2bfloat16_rn(a * (1.f - 0.5f * sf * ma) * 0.125f);
    qp[lane + 32] = __float2bfloat16_rn(c * (1.f - 0.5f * sf * mc) * 0.125f);
}

// ---------------- bf16 tensor-core causal flash attention ----------------
// BQ=128, BK=64, 256 threads (8 warps), ldmatrix + m16n8k16.
#define FSH 72
#define FA_SMEM ((128 + 64 + 64 + 128) * FSH * 2)   // 55296 bytes

__global__ __launch_bounds__(256) void flash_tc(
    const bf16* __restrict__ QKV, bf16* __restrict__ O)
{
    extern __shared__ char smc[];
    bf16* Qs = (bf16*)smc;            // [128][FSH]
    bf16* Ks = Qs + 128 * FSH;        // [64][FSH]
    bf16* Vt = Qs + 192 * FSH;        // [64 d][FSH j] (transposed)
    bf16* Ps = Qs + 256 * FSH;        // [128][FSH]
    unsigned smQ = (unsigned)__cvta_generic_to_shared(Qs);
    unsigned smK = smQ + 128 * FSH * 2;
    unsigned smV = smQ + 192 * FSH * 2;
    unsigned smP = smQ + 256 * FSH * 2;

    int tid = threadIdx.x, lane = tid & 31, wid = tid >> 5;
    int g = lane >> 2, t = lane & 3;
    int lrow = lane & 15, lk8 = (lane >> 4) << 3;
    int bid = blockIdx.x;
    int qb = 15 - bid / 24;           // long blocks first
    int bh = bid % 24;
    int b = bh / NHEAD, h = bh % NHEAD;

    const bf16* Qp = QKV + (size_t)(b * SEQL + qb * 128) * QKVLD + h * DHEAD;
    const bf16* Kp = QKV + (size_t)(b * SEQL) * QKVLD + DIM + h * DHEAD;
    const bf16* Vp = Kp + DIM;

    // load Q tile (128 x 64 bf16)
    #pragma unroll
    for (int it = 0; it < 4; it++) {
        int idx = tid + it * 256;
        int r = idx >> 3, c8 = (idx & 7) * 8;
        *(uint4*)&Qs[r * FSH + c8] = *(const uint4*)(Qp + (size_t)r * QKVLD + c8);
    }

    float oacc[8][4] = {};
    float mrun[2] = {-1e30f, -1e30f}, lrun[2] = {0.f, 0.f};
    int rbase = qb * 128 + wid * 16;
    int kmax = 2 * qb + 2;

    for (int kt = 0; kt < kmax; kt++) {
        __syncthreads();
        #pragma unroll
        for (int it = 0; it < 2; it++) {
            int idx = tid + it * 256;
            int r = idx >> 3, c8 = (idx & 7) * 8;
            *(uint4*)&Ks[r * FSH + c8] =
                *(const uint4*)(Kp + (size_t)(kt * 64 + r) * QKVLD + c8);
            uint4 vv = *(const uint4*)(Vp + (size_t)(kt * 64 + r) * QKVLD + c8);
            const bf16* vh = (const bf16*)&vv;
            #pragma unroll
            for (int e = 0; e < 8; e++)
                Vt[(c8 + e) * FSH + r] = vh[e];
        }
        __syncthreads();

        // S = Q @ K^T  (scale pre-folded into Q)
        float s[8][4] = {};
        #pragma unroll
        for (int ks = 0; ks < 4; ks++) {
            unsigned aq[4], bk[4][4];
            ldsm4(aq, smQ + ((wid*16 + lrow)*FSH + ks*16 + lk8)*2);
            #pragma unroll
            for (int p = 0; p < 4; p++)
                ldsm4(bk[p], smK + ((p*16 + lrow)*FSH + ks*16 + lk8)*2);
            #pragma unroll
            for (int nt = 0; nt < 8; nt++)
                mma16(s[nt], aq, bk[nt>>1][nt&1], bk[nt>>1][(nt&1)+2]);
        }

        if (kt * 64 + 63 > rbase) {
            int r0 = rbase + g, r1 = r0 + 8;
            #pragma unroll
            for (int nt = 0; nt < 8; nt++) {
                int c0 = kt * 64 + nt * 8 + t * 2;
                if (c0     > r0) s[nt][0] = -1e30f;
                if (c0 + 1 > r0) s[nt][1] = -1e30f;
                if (c0     > r1) s[nt][2] = -1e30f;
                if (c0 + 1 > r1) s[nt][3] = -1e30f;
            }
        }

        #pragma unroll
        for (int r = 0; r < 2; r++) {
            float rm = -1e30f;
            #pragma unroll
            for (int nt = 0; nt < 8; nt++)
                rm = fmaxf(rm, fmaxf(s[nt][2*r], s[nt][2*r + 1]));
            rm = fmaxf(rm, __shfl_xor_sync(0xffffffffu, rm, 1));
            rm = fmaxf(rm, __shfl_xor_sync(0xffffffffu, rm, 2));
            float mn = fmaxf(mrun[r], rm);
            float sc = __expf(mrun[r] - mn);
            float rs = 0.f;
            #pragma unroll
            for (int nt = 0; nt < 8; nt++) {
                s[nt][2*r]     = __expf(s[nt][2*r]     - mn);
                s[nt][2*r + 1] = __expf(s[nt][2*r + 1] - mn);
                rs += s[nt][2*r] + s[nt][2*r + 1];
            }
            rs += __shfl_xor_sync(0xffffffffu, rs, 1);
            rs += __shfl_xor_sync(0xffffffffu, rs, 2);
            lrun[r] = lrun[r] * sc + rs;
            mrun[r] = mn;
            #pragma unroll
            for (int nt = 0; nt < 8; nt++) {
                oacc[nt][2*r]     *= sc;
                oacc[nt][2*r + 1] *= sc;
            }
        }

        // stage P (warp-private 16 x 64 slice) as bf16
        #pragma unroll
        for (int nt = 0; nt < 8; nt++) {
            int c = nt * 8 + t * 2;
            *(__nv_bfloat162*)&Ps[(wid*16 + g    ) * FSH + c] = pack_bf2(s[nt][0], s[nt][1]);
            *(__nv_bfloat162*)&Ps[(wid*16 + g + 8) * FSH + c] = pack_bf2(s[nt][2], s[nt][3]);
        }
        __syncwarp();

        // O += P @ V
        #pragma unroll
        for (int ks = 0; ks < 4; ks++) {
            unsigned ap[4], bv[4][4];
            ldsm4(ap, smP + ((wid*16 + lrow)*FSH + ks*16 + lk8)*2);
            #pragma unroll
            for (int p = 0; p < 4; p++)
                ldsm4(bv[p], smV + ((p*16 + lrow)*FSH + ks*16 + lk8)*2);
            #pragma unroll
            for (int nt = 0; nt < 8; nt++)
                mma16(oacc[nt], ap, bv[nt>>1][nt&1], bv[nt>>1][(nt&1)+2]);
        }
    }

    float i0 = 1.f / lrun[0], i1 = 1.f / lrun[1];
    size_t grow0 = (size_t)b * SEQL + qb * 128 + wid * 16 + g;
    #pragma unroll
    for (int nt = 0; nt < 8; nt++) {
        int c = h * DHEAD + nt * 8 + t * 2;
        *(__nv_bfloat162*)&O[grow0 * DIM + c] =
            pack_bf2(oacc[nt][0] * i0, oacc[nt][1] * i0);
        *(__nv_bfloat162*)&O[(grow0 + 8) * DIM + c] =
            pack_bf2(oacc[nt][2] * i1, oacc[nt][3] * i1);
    }
}

// ---------------- host launcher ----------------
extern "C" void kernel_launch(void* const* d_in, const int* in_sizes, int n_in,
                              void* d_out, int out_size)
{
    const float* x    = (const float*)d_in[0];
    const void*  tmsk = d_in[2];
    const float* Wq   = (const float*)d_in[3];
    const float* Wk   = (const float*)d_in[4];
    const float* Wv   = (const float*)d_in[5];
    const float* Wo   = (const float*)d_in[6];
    const float* w1   = (const float*)d_in[7];
    const float* w2   = (const float*)d_in[8];
    const float* w1t  = (const float*)d_in[9];
    const float* w2t  = (const float*)d_in[10];
    const float* w1s  = (const float*)d_in[11];
    const float* w2s  = (const float*)d_in[12];
    const float* n1w  = (const float*)d_in[13];
    const float* n1b  = (const float*)d_in[14];
    const float* n2w  = (const float*)d_in[15];
    const float* n2b  = (const float*)d_in[16];
    float* out = (float*)d_out;

    bf16 *p_xn, *p_qkv, *p_attn, *p_xm, *p_xs, *p_hcat;
    bf16 *p_wqkv, *p_w1cat, *p_w2cat, *p_woc;
    float *p_x1;
    cudaGetSymbolAddress((void**)&p_xn,    g_xn);
    cudaGetSymbolAddress((void**)&p_qkv,   g_qkv);
    cudaGetSymbolAddress((void**)&p_attn,  g_attn);
    cudaGetSymbolAddress((void**)&p_x1,    g_x1);
    cudaGetSymbolAddress((void**)&p_xm,    g_xm);
    cudaGetSymbolAddress((void**)&p_xs,    g_xs);
    cudaGetSymbolAddress((void**)&p_hcat,  g_hcat);
    cudaGetSymbolAddress((void**)&p_wqkv,  g_wqkv);
    cudaGetSymbolAddress((void**)&p_w1cat, g_w1cat);
    cudaGetSymbolAddress((void**)&p_w2cat, g_w2cat);
    cudaGetSymbolAddress((void**)&p_woc,   g_woc);

    static int attr_done = 0;
    if (!attr_done) {
        cudaFuncSetAttribute((const void*)tgemm<4,1>, cudaFuncAttributeMaxDynamicSharedMemorySize, GEMM_SMEM_MT4);
        cudaFuncSetAttribute((const void*)tgemm<4,0>, cudaFuncAttributeMaxDynamicSharedMemorySize, GEMM_SMEM_MT4);
        cudaFuncSetAttribute((const void*)tgemm<2,0>, cudaFuncAttributeMaxDynamicSharedMemorySize, GEMM_SMEM_MT2);
        cudaFuncSetAttribute((const void*)ffn_up,     cudaFuncAttributeMaxDynamicSharedMemorySize, GEMM_SMEM_MT4);
        cudaFuncSetAttribute((const void*)flash_tc,   cudaFuncAttributeMaxDynamicSharedMemorySize, FA_SMEM);
        attr_done = 1;
    }

    decode_mask_kernel<<<1, 256>>>(tmsk);

    // weight prep (concat + bf16 conversion)
    prep_wqkv <<<QKVLD*DIM/1024, 256>>>(Wq, Wk, Wv, p_wqkv);
    prep_w1cat<<<(size_t)KCAT*DIM/1024, 256>>>(w1, w1t, w1s, p_w1cat);
    prep_w2cat<<<(size_t)DIM*KCAT/1024, 256>>>(w2, w2t, w2s, p_w2cat);
    prep_woc  <<<DIM*DIM/1024, 256>>>(Wo, p_woc);

    // ---- attention path ----
    mink_norm_kernel<0><<<NROWS, 256>>>(x, n1w, n1b, p_xn, nullptr, nullptr);

    tgemm<4,1><<<dim3(QKVLD/128, NROWS/128), 256, GEMM_SMEM_MT4>>>(
        p_xn, p_wqkv, p_qkv, nullptr, DIM, QKVLD, 1.f);
    qeff_kernel<<<(NROWS * NHEAD * 32) / 256, 256>>>(p_qkv);

    flash_tc<<<16 * 24, 256, FA_SMEM>>>(p_qkv, p_attn);

    // x1 = x + attn @ Wo^T   (MT=2 -> 384 blocks, full waves)
    tgemm<2,0><<<dim3(DIM/128, NROWS/64), 256, GEMM_SMEM_MT2>>>(
        p_attn, p_woc, p_x1, x, DIM, DIM, 1.f);

    // ---- FFN path ----
    mink_norm_kernel<1><<<NROWS, 256>>>(p_x1, n2w, n2b, p_xn, p_xm, p_xs);

    ffn_up<<<dim3(KCAT/128, NROWS/128), 256, GEMM_SMEM_MT4>>>(
        p_xn, p_xm, p_xs, p_w1cat, p_hcat);

    // out = x1 + 0.5 * hcat @ w2cat^T   (single K=6144 GEMM, MT=2)
    tgemm<2,0><<<dim3(DIM/128, NROWS/64), 256, GEMM_SMEM_MT2>>>(
        p_hcat, p_w2cat, out, p_x1, KCAT, DIM, 0.5f);
}

// round 8
// speedup vs baseline: 6.3285x; 1.0488x over previous
#include <cuda_runtime.h>
#include <cuda_bf16.h>
#include <math.h>

typedef __nv_bfloat16 bf16;

// Problem constants
#define BATCH 2
#define SEQL  2048
#define DIM   768
#define NHEAD 12
#define DHEAD 64
#define DFF   3072
#define DFFH  1536
#define NROWS (BATCH*SEQL)          // 4096
#define QKVLD 2304                  // concat QKV row stride
#define KCAT  6144                  // concat FFN hidden width

// ---------------- scratch (static device globals; no allocation) ----------------
__device__ float g_mask [DIM];
__device__ bf16  g_xn   [NROWS*DIM];
__device__ bf16  g_qkv  [(size_t)NROWS*QKVLD];
__device__ bf16  g_attn [NROWS*DIM];
__device__ float g_x1   [NROWS*DIM];
__device__ bf16  g_xm   [NROWS*DIM];
__device__ bf16  g_xs   [NROWS*DIM];
__device__ bf16  g_hcat [(size_t)NROWS*KCAT];
__device__ bf16  g_wqkv [QKVLD*DIM];
__device__ bf16  g_w1cat[(size_t)KCAT*DIM];
__device__ bf16  g_w2cat[(size_t)DIM*KCAT];
__device__ bf16  g_woc  [DIM*DIM];

// ---------------- helpers ----------------
__device__ __forceinline__ float gelu_f(float x) {
    return 0.5f * x * (1.f + erff(x * 0.70710678118654752f));
}
__device__ __forceinline__ float silu_f(float x) {
    return x / (1.f + expf(-x));
}
__device__ __forceinline__ __nv_bfloat162 pack_bf2(float a, float b) {
    return __float22bfloat162_rn(make_float2(a, b));
}

// m16n8k16 bf16 mma: D += A(16x16 row) * B(16x8 col-of-NT)
__device__ __forceinline__ void mma16(float* c, const unsigned* a,
                                      unsigned b0, unsigned b1) {
    asm volatile(
        "mma.sync.aligned.m16n8k16.row.col.f32.bf16.bf16.f32 "
        "{%0,%1,%2,%3}, {%4,%5,%6,%7}, {%8,%9}, {%0,%1,%2,%3};\n"
        : "+f"(c[0]), "+f"(c[1]), "+f"(c[2]), "+f"(c[3])
        : "r"(a[0]), "r"(a[1]), "r"(a[2]), "r"(a[3]), "r"(b0), "r"(b1));
}
__device__ __forceinline__ void ldsm4(unsigned* r, unsigned addr) {
    asm volatile("ldmatrix.sync.aligned.m8n8.x4.shared.b16 {%0,%1,%2,%3}, [%4];"
        : "=r"(r[0]), "=r"(r[1]), "=r"(r[2]), "=r"(r[3]) : "r"(addr));
}
__device__ __forceinline__ void cp16(unsigned dst, const void* src) {
    asm volatile("cp.async.cg.shared.global [%0], [%1], 16;\n" :: "r"(dst), "l"(src));
}
__device__ __forceinline__ void cp_commit() { asm volatile("cp.async.commit_group;\n"); }
template<int N> __device__ __forceinline__ void cp_wait() {
    asm volatile("cp.async.wait_group %0;\n" :: "n"(N));
}

// ---------------- timelike_mask decode (dtype-robust: f32 / i32 / bool8) ----------------
__global__ void decode_mask_kernel(const void* __restrict__ raw) {
    __shared__ int cls;
    if (threadIdx.x == 0) {
        const unsigned* w = (const unsigned*)raw;
        int isFloat = 0, isByte = 0;
        for (int i = 0; i < 192; i++) {
            unsigned v = w[i];
            if (v == 0x3F800000u) isFloat = 1;
            if (v != 0u) {
                bool bytes01 = true, hi = false;
                for (int b = 0; b < 4; b++) {
                    unsigned by = (v >> (8*b)) & 0xffu;
                    if (by > 1u) bytes01 = false;
                    if (b > 0 && by) hi = true;
                }
                if (bytes01 && hi) isByte = 1;
            }
        }
        cls = isFloat ? 0 : (isByte ? 2 : 1);
    }
    __syncthreads();
    int c = cls;
    for (int i = threadIdx.x; i < DIM; i += blockDim.x) {
        float mv;
        if (c == 0)      mv = ((const float*)raw)[i];
        else if (c == 1) mv = (float)(((const int*)raw)[i] != 0);
        else             mv = (float)(((const unsigned char*)raw)[i] != 0);
        g_mask[i] = mv;
    }
}

// ---------------- weight prep: concat + bf16 convert (vectorized) ----------------
__global__ __launch_bounds__(256) void prep_wqkv(
    const float* __restrict__ Wq, const float* __restrict__ Wk,
    const float* __restrict__ Wv, bf16* __restrict__ o)
{
    int i4 = blockIdx.x * 256 + threadIdx.x;
    int i = i4 * 4;
    int r = i / DIM, c = i % DIM;
    const float* src = (r < DIM) ? (Wq + r*DIM + c)
                     : (r < 2*DIM) ? (Wk + (r-DIM)*DIM + c) : (Wv + (r-2*DIM)*DIM + c);
    float4 v = *(const float4*)src;
    *(__nv_bfloat162*)&o[i]     = pack_bf2(v.x, v.y);
    *(__nv_bfloat162*)&o[i + 2] = pack_bf2(v.z, v.w);
}
__global__ __launch_bounds__(256) void prep_w1cat(
    const float* __restrict__ w1, const float* __restrict__ w1t,
    const float* __restrict__ w1s, bf16* __restrict__ o)
{
    int i4 = blockIdx.x * 256 + threadIdx.x;
    int i = i4 * 4;
    int r = i / DIM, c = i % DIM;
    const float* src = (r < DFF) ? (w1 + r*DIM + c)
                     : (r < DFF+DFFH) ? (w1t + (r-DFF)*DIM + c)
                     : (w1s + (size_t)(r-DFF-DFFH)*DIM + c);
    float4 v = *(const float4*)src;
    *(__nv_bfloat162*)&o[i]     = pack_bf2(v.x, v.y);
    *(__nv_bfloat162*)&o[i + 2] = pack_bf2(v.z, v.w);
}
__global__ __launch_bounds__(256) void prep_w2cat(
    const float* __restrict__ w2, const float* __restrict__ w2t,
    const float* __restrict__ w2s, bf16* __restrict__ o)
{
    int i4 = blockIdx.x * 256 + threadIdx.x;
    size_t i = (size_t)i4 * 4;
    int r = (int)(i / KCAT), c = (int)(i % KCAT);
    const float* src = (c < DFF) ? (w2 + (size_t)r*DFF + c)
                     : (c < DFF+DFFH) ? (w2t + (size_t)r*DFFH + c - DFF)
                     : (w2s + (size_t)r*DFFH + c - DFF - DFFH);
    float4 v = *(const float4*)src;
    *(__nv_bfloat162*)&o[i]     = pack_bf2(v.x, v.y);
    *(__nv_bfloat162*)&o[i + 2] = pack_bf2(v.z, v.w);
}
__global__ __launch_bounds__(256) void prep_woc(
    const float* __restrict__ Wo, bf16* __restrict__ o)
{
    int i = (blockIdx.x * 256 + threadIdx.x) * 4;
    float4 v = *(const float4*)(Wo + i);
    *(__nv_bfloat162*)&o[i]     = pack_bf2(v.x, v.y);
    *(__nv_bfloat162*)&o[i + 2] = pack_bf2(v.z, v.w);
}

// ---------------- Minkowski LayerNorm (bf16 output; optional mask split) ----------------
template<int SPLIT>
__global__ __launch_bounds__(256) void mink_norm_kernel(
    const float* __restrict__ x, const float* __restrict__ w,
    const float* __restrict__ bb, bf16* __restrict__ out,
    bf16* __restrict__ om, bf16* __restrict__ os)
{
    __shared__ float sA[8], sB[8];
    int row = blockIdx.x, t = threadIdx.x;
    const float* xr = x + (size_t)row * DIM;
    float v0 = xr[t], v1 = xr[t+256], v2 = xr[t+512];
    int lane = t & 31, wp = t >> 5;

    float s = v0 + v1 + v2;
    #pragma unroll
    for (int o = 16; o; o >>= 1) s += __shfl_xor_sync(0xffffffffu, s, o);
    if (!lane) sA[wp] = s;
    __syncthreads();
    float tot = 0.f;
    #pragma unroll
    for (int i = 0; i < 8; i++) tot += sA[i];
    float mean = tot * (1.f / DIM);

    float c0 = v0 - mean, c1 = v1 - mean, c2 = v2 - mean;
    float m0 = g_mask[t], m1 = g_mask[t+256], m2 = g_mask[t+512];
    float s2  = c0*c0 + c1*c1 + c2*c2;
    float s2m = c0*c0*m0 + c1*c1*m1 + c2*c2*m2;
    #pragma unroll
    for (int o = 16; o; o >>= 1) {
        s2  += __shfl_xor_sync(0xffffffffu, s2,  o);
        s2m += __shfl_xor_sync(0xffffffffu, s2m, o);
    }
    __syncthreads();
    if (!lane) { sA[wp] = s2; sB[wp] = s2m; }
    __syncthreads();
    float S2 = 0.f, S2m = 0.f;
    #pragma unroll
    for (int i = 0; i < 8; i++) { S2 += sA[i]; S2m += sB[i]; }

    float var = S2 * (1.f / DIM);
    float eta = S2 - 2.f * S2m;
    float kk  = 0.5f * (rsqrtf(var + 1e-5f) + rsqrtf(fabsf(eta) + 1e-5f));

    float y0 = w[t]     * (c0 * kk) + bb[t];
    float y1 = w[t+256] * (c1 * kk) + bb[t+256];
    float y2 = w[t+512] * (c2 * kk) + bb[t+512];
    size_t o0 = (size_t)row * DIM + t;
    out[o0]     = __float2bfloat16_rn(y0);
    out[o0+256] = __float2bfloat16_rn(y1);
    out[o0+512] = __float2bfloat16_rn(y2);
    if (SPLIT) {
        om[o0]     = __float2bfloat16_rn(y0 * m0);
        om[o0+256] = __float2bfloat16_rn(y1 * m1);
        om[o0+512] = __float2bfloat16_rn(y2 * m2);
        os[o0]     = __float2bfloat16_rn(y0 * (1.f - m0));
        os[o0+256] = __float2bfloat16_rn(y1 * (1.f - m1));
        os[o0+512] = __float2bfloat16_rn(y2 * (1.f - m2));
    }
}

// ---------------- bf16 tensor-core NT GEMM core (2-stage cp.async, BK=64) ----------------
// C[M,N] = A[M,K] @ B[N,K]^T.  MT = m-tiles per warp (BM = MT*32), BN = 128.
#define BKH 64                        // k elements per stage
#define LDH 72                        // smem row stride in halves (conflict-free)
#define STAGES 2

template<int MT>
__device__ __forceinline__ void gemm_core_bf(
    const bf16* __restrict__ A, const bf16* __restrict__ B,
    int K, int bm, int bn, float (&acc)[MT][4][4])
{
    constexpr int AROWS = MT * 32;
    constexpr int TILEA = AROWS * LDH;            // halves
    constexpr int TILEB = 128 * LDH;
    constexpr int STB   = (TILEA + TILEB) * 2;    // stage bytes
    extern __shared__ char shc[];
    unsigned shBase = (unsigned)__cvta_generic_to_shared(shc);

    int tid = threadIdx.x, lane = tid & 31, wid = tid >> 5;
    int wm = wid & 1, wn = wid >> 1;              // 2 x 4 warp grid
    int lr = tid >> 3;                            // 0..31
    int lc = (tid & 7) * 8;                       // halves chunk 0..56

    const bf16* Ap = A + (size_t)(bm + lr) * K + lc;
    const bf16* Bp = B + (size_t)(bn + lr) * K + lc;

    int nk = K / BKH;
    // preload stage 0
    {
        unsigned st = shBase;
        #pragma unroll
        for (int p = 0; p < MT; p++)
            cp16(st + ((lr + 32*p)*LDH + lc)*2, Ap + (size_t)32*p*K);
        #pragma unroll
        for (int p = 0; p < 4; p++)
            cp16(st + TILEA*2 + ((lr + 32*p)*LDH + lc)*2, Bp + (size_t)32*p*K);
        cp_commit();
    }

    int lrow = lane & 15, lk8 = (lane >> 4) << 3;
    for (int kt = 0; kt < nk; kt++) {
        cp_wait<0>();
        __syncthreads();

        int pf = kt + 1;
        if (pf < nk) {
            unsigned st = shBase + (pf & 1) * STB;
            const bf16* a = Ap + pf * BKH;
            const bf16* b = Bp + pf * BKH;
            #pragma unroll
            for (int p = 0; p < MT; p++)
                cp16(st + ((lr + 32*p)*LDH + lc)*2, a + (size_t)32*p*K);
            #pragma unroll
            for (int p = 0; p < 4; p++)
                cp16(st + TILEA*2 + ((lr + 32*p)*LDH + lc)*2, b + (size_t)32*p*K);
        }
        cp_commit();

        unsigned sA = shBase + (kt & 1) * STB;
        unsigned sB = sA + TILEA * 2;
        #pragma unroll
        for (int ks = 0; ks < 4; ks++) {
            unsigned af[MT][4], bq[2][4];
            #pragma unroll
            for (int mt = 0; mt < MT; mt++)
                ldsm4(af[mt], sA + ((wm*(MT*16) + mt*16 + lrow)*LDH + ks*16 + lk8)*2);
            #pragma unroll
            for (int p = 0; p < 2; p++)
                ldsm4(bq[p], sB + ((wn*32 + p*16 + lrow)*LDH + ks*16 + lk8)*2);
            #pragma unroll
            for (int mt = 0; mt < MT; mt++)
                #pragma unroll
                for (int nt = 0; nt < 4; nt++)
                    mma16(acc[mt][nt], af[mt],
                          bq[nt>>1][nt&1], bq[nt>>1][(nt&1)+2]);
        }
    }
}

// epilogue: act (uniform), alpha, optional residual; OT: 0 fp32, 1 bf16
template<int MT, int OT>
__device__ __forceinline__ void store_epi(
    float (&acc)[MT][4][4], void* Cv, const float* __restrict__ resid,
    int ldc, float alpha, int bm, int bn, int act)
{
    int tid = threadIdx.x, lane = tid & 31, wid = tid >> 5;
    int wm = wid & 1, wn = wid >> 1;
    int g = lane >> 2, t = lane & 3;
    #pragma unroll
    for (int mt = 0; mt < MT; mt++) {
        int r0 = bm + wm*(MT*16) + mt*16 + g;
        #pragma unroll
        for (int nt = 0; nt < 4; nt++) {
            int c = bn + wn*32 + nt*8 + t*2;
            #pragma unroll
            for (int hh = 0; hh < 2; hh++) {
                float v0 = acc[mt][nt][2*hh];
                float v1 = acc[mt][nt][2*hh + 1];
                if (act == 1) { v0 = gelu_f(v0); v1 = gelu_f(v1); }
                else if (act == 2) { v0 = silu_f(v0); v1 = silu_f(v1); }
                v0 *= alpha; v1 *= alpha;
                size_t idx = (size_t)(r0 + 8*hh) * ldc + c;
                if (OT == 0) {
                    if (resid) {
                        float2 rv = *(const float2*)(resid + idx);
                        v0 += rv.x; v1 += rv.y;
                    }
                    *(float2*)((float*)Cv + idx) = make_float2(v0, v1);
                } else {
                    *(__nv_bfloat162*)((bf16*)Cv + idx) = pack_bf2(v0, v1);
                }
            }
        }
    }
}

template<int MT, int OT>
__global__ __launch_bounds__(256, (MT == 2) ? 3 : 2) void tgemm(
    const bf16* __restrict__ A, const bf16* __restrict__ B,
    void* __restrict__ C, const float* __restrict__ resid,
    int K, int ldc, float alpha)
{
    float acc[MT][4][4] = {};
    int bm = blockIdx.y * (MT*32), bn = blockIdx.x * 128;
    gemm_core_bf<MT>(A, B, K, bm, bn, acc);
    store_epi<MT, OT>(acc, C, resid, ldc, alpha, bm, bn, 0);
}

// fused FFN up-projection: per-block-column A-pointer + activation select
__global__ __launch_bounds__(256, 2) void ffn_up(
    const bf16* __restrict__ xn, const bf16* __restrict__ xm,
    const bf16* __restrict__ xs, const bf16* __restrict__ w1cat,
    bf16* __restrict__ hcat)
{
    int bn = blockIdx.x * 128, bm = blockIdx.y * 128;
    const bf16* A; int act;
    if (bn < DFF)             { A = xn; act = 1; }
    else if (bn < DFF + DFFH) { A = xm; act = 2; }
    else                      { A = xs; act = 1; }
    float acc[4][4][4] = {};
    gemm_core_bf<4>(A, w1cat, DIM, bm, bn, acc);
    store_epi<4, 1>(acc, hcat, nullptr, KCAT, 1.f, bm, bn, act);
}

#define GEMM_SMEM_MT4 (STAGES * (4*32 + 128) * LDH * 2)   // 73728
#define GEMM_SMEM_MT2 (STAGES * (2*32 + 128) * LDH * 2)   // 55296

// ---------------- fold Lorentz sf + 1/sqrt(DH) into Q (bf16) ----------------
__global__ __launch_bounds__(256) void qeff_kernel(bf16* __restrict__ qkv)
{
    int gw   = (blockIdx.x * blockDim.x + threadIdx.x) >> 5;
    int lane = threadIdx.x & 31;
    if (gw >= NROWS * NHEAD) return;
    int row = gw / NHEAD, h = gw % NHEAD;
    bf16* qp = qkv + (size_t)row * QKVLD + h * DHEAD;
    float a = __bfloat162float(qp[lane]);
    float c = __bfloat162float(qp[lane + 32]);
    float ma = g_mask[h * DHEAD + lane], mc = g_mask[h * DHEAD + lane + 32];
    float qn2  = a*a + c*c;
    float qtn2 = a*a*ma + c*c*mc;
    #pragma unroll
    for (int o = 16; o; o >>= 1) {
        qn2  += __shfl_xor_sync(0xffffffffu, qn2,  o);
        qtn2 += __shfl_xor_sync(0xffffffffu, qtn2, o);
    }
    float qtn = sqrtf(qtn2);
    float sf  = (qtn > 1e-6f) ? sqrtf(qn2) / fmaxf(qtn, 1e-8f) : 0.f;
    qp[lane]      = __float2bfloat16_rn(a * (1.f - 0.5f * sf * ma) * 0.125f);
    qp[lane + 32] = __float2bfloat16_rn(c * (1.f - 0.5f * sf * mc) * 0.125f);
}

// ---------------- bf16 tensor-core causal flash attention ----------------
// BQ=128, BK=64, 256 threads (8 warps), ldmatrix + m16n8k16.
#define FSH 72
#define FA_SMEM ((128 + 64 + 64 + 128) * FSH * 2)   // 55296 bytes

__global__ __launch_bounds__(256) void flash_tc(
    const bf16* __restrict__ QKV, bf16* __restrict__ O)
{
    extern __shared__ char smc[];
    bf16* Qs = (bf16*)smc;            // [128][FSH]
    bf16* Ks = Qs + 128 * FSH;        // [64][FSH]
    bf16* Vt = Qs + 192 * FSH;        // [64 d][FSH j] (transposed)
    bf16* Ps = Qs + 256 * FSH;        // [128][FSH]
    unsigned smQ = (unsigned)__cvta_generic_to_shared(Qs);
    unsigned smK = smQ + 128 * FSH * 2;
    unsigned smV = smQ + 192 * FSH * 2;
    unsigned smP = smQ + 256 * FSH * 2;

    int tid = threadIdx.x, lane = tid & 31, wid = tid >> 5;
    int g = lane >> 2, t = lane & 3;
    int lrow = lane & 15, lk8 = (lane >> 4) << 3;
    int bid = blockIdx.x;
    int qb = 15 - bid / 24;           // long blocks first
    int bh = bid % 24;
    int b = bh / NHEAD, h = bh % NHEAD;

    const bf16* Qp = QKV + (size_t)(b * SEQL + qb * 128) * QKVLD + h * DHEAD;
    const bf16* Kp = QKV + (size_t)(b * SEQL) * QKVLD + DIM + h * DHEAD;
    const bf16* Vp = Kp + DIM;

    // load Q tile (128 x 64 bf16)
    #pragma unroll
    for (int it = 0; it < 4; it++) {
        int idx = tid + it * 256;
        int r = idx >> 3, c8 = (idx & 7) * 8;
        *(uint4*)&Qs[r * FSH + c8] = *(const uint4*)(Qp + (size_t)r * QKVLD + c8);
    }

    float oacc[8][4] = {};
    float mrun[2] = {-1e30f, -1e30f}, lrun[2] = {0.f, 0.f};
    int rbase = qb * 128 + wid * 16;
    int kmax = 2 * qb + 2;

    for (int kt = 0; kt < kmax; kt++) {
        __syncthreads();
        #pragma unroll
        for (int it = 0; it < 2; it++) {
            int idx = tid + it * 256;
            int r = idx >> 3, c8 = (idx & 7) * 8;
            *(uint4*)&Ks[r * FSH + c8] =
                *(const uint4*)(Kp + (size_t)(kt * 64 + r) * QKVLD + c8);
            uint4 vv = *(const uint4*)(Vp + (size_t)(kt * 64 + r) * QKVLD + c8);
            const bf16* vh = (const bf16*)&vv;
            #pragma unroll
            for (int e = 0; e < 8; e++)
                Vt[(c8 + e) * FSH + r] = vh[e];
        }
        __syncthreads();

        // S = Q @ K^T  (scale pre-folded into Q)
        float s[8][4] = {};
        #pragma unroll
        for (int ks = 0; ks < 4; ks++) {
            unsigned aq[4], bk[4][4];
            ldsm4(aq, smQ + ((wid*16 + lrow)*FSH + ks*16 + lk8)*2);
            #pragma unroll
            for (int p = 0; p < 4; p++)
                ldsm4(bk[p], smK + ((p*16 + lrow)*FSH + ks*16 + lk8)*2);
            #pragma unroll
            for (int nt = 0; nt < 8; nt++)
                mma16(s[nt], aq, bk[nt>>1][nt&1], bk[nt>>1][(nt&1)+2]);
        }

        if (kt * 64 + 63 > rbase) {
            int r0 = rbase + g, r1 = r0 + 8;
            #pragma unroll
            for (int nt = 0; nt < 8; nt++) {
                int c0 = kt * 64 + nt * 8 + t * 2;
                if (c0     > r0) s[nt][0] = -1e30f;
                if (c0 + 1 > r0) s[nt][1] = -1e30f;
                if (c0     > r1) s[nt][2] = -1e30f;
                if (c0 + 1 > r1) s[nt][3] = -1e30f;
            }
        }

        #pragma unroll
        for (int r = 0; r < 2; r++) {
            float rm = -1e30f;
            #pragma unroll
            for (int nt = 0; nt < 8; nt++)
                rm = fmaxf(rm, fmaxf(s[nt][2*r], s[nt][2*r + 1]));
            rm = fmaxf(rm, __shfl_xor_sync(0xffffffffu, rm, 1));
            rm = fmaxf(rm, __shfl_xor_sync(0xffffffffu, rm, 2));
            float mn = fmaxf(mrun[r], rm);
            float sc = __expf(mrun[r] - mn);
            float rs = 0.f;
            #pragma unroll
            for (int nt = 0; nt < 8; nt++) {
                s[nt][2*r]     = __expf(s[nt][2*r]     - mn);
                s[nt][2*r + 1] = __expf(s[nt][2*r + 1] - mn);
                rs += s[nt][2*r] + s[nt][2*r + 1];
            }
            rs += __shfl_xor_sync(0xffffffffu, rs, 1);
            rs += __shfl_xor_sync(0xffffffffu, rs, 2);
            lrun[r] = lrun[r] * sc + rs;
            mrun[r] = mn;
            #pragma unroll
            for (int nt = 0; nt < 8; nt++) {
                oacc[nt][2*r]     *= sc;
                oacc[nt][2*r + 1] *= sc;
            }
        }

        // stage P (warp-private 16 x 64 slice) as bf16
        #pragma unroll
        for (int nt = 0; nt < 8; nt++) {
            int c = nt * 8 + t * 2;
            *(__nv_bfloat162*)&Ps[(wid*16 + g    ) * FSH + c] = pack_bf2(s[nt][0], s[nt][1]);
            *(__nv_bfloat162*)&Ps[(wid*16 + g + 8) * FSH + c] = pack_bf2(s[nt][2], s[nt][3]);
        }
        __syncwarp();

        // O += P @ V
        #pragma unroll
        for (int ks = 0; ks < 4; ks++) {
            unsigned ap[4], bv[4][4];
            ldsm4(ap, smP + ((wid*16 + lrow)*FSH + ks*16 + lk8)*2);
            #pragma unroll
            for (int p = 0; p < 4; p++)
                ldsm4(bv[p], smV + ((p*16 + lrow)*FSH + ks*16 + lk8)*2);
            #pragma unroll
            for (int nt = 0; nt < 8; nt++)
                mma16(oacc[nt], ap, bv[nt>>1][nt&1], bv[nt>>1][(nt&1)+2]);
        }
    }

    float i0 = 1.f / lrun[0], i1 = 1.f / lrun[1];
    size_t grow0 = (size_t)b * SEQL + qb * 128 + wid * 16 + g;
    #pragma unroll
    for (int nt = 0; nt < 8; nt++) {
        int c = h * DHEAD + nt * 8 + t * 2;
        *(__nv_bfloat162*)&O[grow0 * DIM + c] =
            pack_bf2(oacc[nt][0] * i0, oacc[nt][1] * i0);
        *(__nv_bfloat162*)&O[(grow0 + 8) * DIM + c] =
            pack_bf2(oacc[nt][2] * i1, oacc[nt][3] * i1);
    }
}

// ---------------- host launcher ----------------
extern "C" void kernel_launch(void* const* d_in, const int* in_sizes, int n_in,
                              void* d_out, int out_size)
{
    const float* x    = (const float*)d_in[0];
    const void*  tmsk = d_in[2];
    const float* Wq   = (const float*)d_in[3];
    const float* Wk   = (const float*)d_in[4];
    const float* Wv   = (const float*)d_in[5];
    const float* Wo   = (const float*)d_in[6];
    const float* w1   = (const float*)d_in[7];
    const float* w2   = (const float*)d_in[8];
    const float* w1t  = (const float*)d_in[9];
    const float* w2t  = (const float*)d_in[10];
    const float* w1s  = (const float*)d_in[11];
    const float* w2s  = (const float*)d_in[12];
    const float* n1w  = (const float*)d_in[13];
    const float* n1b  = (const float*)d_in[14];
    const float* n2w  = (const float*)d_in[15];
    const float* n2b  = (const float*)d_in[16];
    float* out = (float*)d_out;

    bf16 *p_xn, *p_qkv, *p_attn, *p_xm, *p_xs, *p_hcat;
    bf16 *p_wqkv, *p_w1cat, *p_w2cat, *p_woc;
    float *p_x1;
    cudaGetSymbolAddress((void**)&p_xn,    g_xn);
    cudaGetSymbolAddress((void**)&p_qkv,   g_qkv);
    cudaGetSymbolAddress((void**)&p_attn,  g_attn);
    cudaGetSymbolAddress((void**)&p_x1,    g_x1);
    cudaGetSymbolAddress((void**)&p_xm,    g_xm);
    cudaGetSymbolAddress((void**)&p_xs,    g_xs);
    cudaGetSymbolAddress((void**)&p_hcat,  g_hcat);
    cudaGetSymbolAddress((void**)&p_wqkv,  g_wqkv);
    cudaGetSymbolAddress((void**)&p_w1cat, g_w1cat);
    cudaGetSymbolAddress((void**)&p_w2cat, g_w2cat);
    cudaGetSymbolAddress((void**)&p_woc,   g_woc);

    static int attr_done = 0;
    if (!attr_done) {
        cudaFuncSetAttribute((const void*)tgemm<4,1>, cudaFuncAttributeMaxDynamicSharedMemorySize, GEMM_SMEM_MT4);
        cudaFuncSetAttribute((const void*)tgemm<4,0>, cudaFuncAttributeMaxDynamicSharedMemorySize, GEMM_SMEM_MT4);
        cudaFuncSetAttribute((const void*)tgemm<2,0>, cudaFuncAttributeMaxDynamicSharedMemorySize, GEMM_SMEM_MT2);
        cudaFuncSetAttribute((const void*)ffn_up,     cudaFuncAttributeMaxDynamicSharedMemorySize, GEMM_SMEM_MT4);
        cudaFuncSetAttribute((const void*)flash_tc,   cudaFuncAttributeMaxDynamicSharedMemorySize, FA_SMEM);
        attr_done = 1;
    }

    decode_mask_kernel<<<1, 256>>>(tmsk);

    // weight prep (concat + bf16 conversion)
    prep_wqkv <<<QKVLD*DIM/1024, 256>>>(Wq, Wk, Wv, p_wqkv);
    prep_w1cat<<<(size_t)KCAT*DIM/1024, 256>>>(w1, w1t, w1s, p_w1cat);
    prep_w2cat<<<(size_t)DIM*KCAT/1024, 256>>>(w2, w2t, w2s, p_w2cat);
    prep_woc  <<<DIM*DIM/1024, 256>>>(Wo, p_woc);

    // ---- attention path ----
    mink_norm_kernel<0><<<NROWS, 256>>>(x, n1w, n1b, p_xn, nullptr, nullptr);

    tgemm<4,1><<<dim3(QKVLD/128, NROWS/128), 256, GEMM_SMEM_MT4>>>(
        p_xn, p_wqkv, p_qkv, nullptr, DIM, QKVLD, 1.f);
    qeff_kernel<<<(NROWS * NHEAD * 32) / 256, 256>>>(p_qkv);

    flash_tc<<<16 * 24, 256, FA_SMEM>>>(p_qkv, p_attn);

    // x1 = x + attn @ Wo^T   (MT=2, 3 blocks/SM -> single wave)
    tgemm<2,0><<<dim3(DIM/128, NROWS/64), 256, GEMM_SMEM_MT2>>>(
        p_attn, p_woc, p_x1, x, DIM, DIM, 1.f);

    // ---- FFN path ----
    mink_norm_kernel<1><<<NROWS, 256>>>(p_x1, n2w, n2b, p_xn, p_xm, p_xs);

    ffn_up<<<dim3(KCAT/128, NROWS/128), 256, GEMM_SMEM_MT4>>>(
        p_xn, p_xm, p_xs, p_w1cat, p_hcat);

    // out = x1 + 0.5 * hcat @ w2cat^T   (single K=6144 GEMM, MT=2)
    tgemm<2,0><<<dim3(DIM/128, NROWS/64), 256, GEMM_SMEM_MT2>>>(
        p_hcat, p_w2cat, out, p_x1, KCAT, DIM, 0.5f);
}